// round 1
// baseline (speedup 1.0000x reference)
#include <cuda_runtime.h>
#include <math.h>

#define BATCH 32
#define CDIM  384
#define HDIM  56
#define HWSZ  3136          // 56*56
#define NTOK  100352        // BATCH*HWSZ
#define HID   1536
#define HEADS 8
#define HD    48
#define GSZ   7             // grid = H / SPARSE
#define SPR   8             // SPARSE

// ---------------- scratch (device globals; no allocation allowed) ----------------
__device__ float g_xt [(size_t)NTOK * CDIM];        // x token-major; becomes x1, x2 (in-place)
__device__ float g_h  [(size_t)NTOK * CDIM];        // LN out / attention out / LN2 out
__device__ float g_qkv[(size_t)NTOK * 3 * CDIM];    // qkv
__device__ float g_m  [(size_t)NTOK * HID];         // fc1 out
__device__ float g_mg [(size_t)NTOK * HID];         // dwconv+gelu out

// ---------------- transpose in: x[B,C,HW] -> xt[B*HW, C] ----------------
__global__ void transpose_in_kernel(const float* __restrict__ x, float* __restrict__ xt) {
    __shared__ float tile[32][33];
    const int b  = blockIdx.z;
    const int p0 = blockIdx.x * 32;   // spatial
    const int c0 = blockIdx.y * 32;   // channel
    const float* xb = x + (size_t)b * CDIM * HWSZ;
#pragma unroll
    for (int i = 0; i < 4; i++) {
        int c = c0 + threadIdx.y + i * 8;
        tile[threadIdx.y + i * 8][threadIdx.x] = xb[(size_t)c * HWSZ + p0 + threadIdx.x];
    }
    __syncthreads();
#pragma unroll
    for (int i = 0; i < 4; i++) {
        int p = p0 + threadIdx.y + i * 8;
        xt[((size_t)b * HWSZ + p) * CDIM + c0 + threadIdx.x] = tile[threadIdx.x][threadIdx.y + i * 8];
    }
}

// ---------------- transpose out: xt[B*HW, C] -> out[B,C,HW] ----------------
__global__ void transpose_out_kernel(const float* __restrict__ xt, float* __restrict__ out) {
    __shared__ float tile[32][33];
    const int b  = blockIdx.z;
    const int p0 = blockIdx.x * 32;
    const int c0 = blockIdx.y * 32;
#pragma unroll
    for (int i = 0; i < 4; i++) {
        int p = p0 + threadIdx.y + i * 8;
        tile[threadIdx.y + i * 8][threadIdx.x] = xt[((size_t)b * HWSZ + p) * CDIM + c0 + threadIdx.x];
    }
    __syncthreads();
    float* ob = out + (size_t)b * CDIM * HWSZ;
#pragma unroll
    for (int i = 0; i < 4; i++) {
        int c = c0 + threadIdx.y + i * 8;
        ob[(size_t)c * HWSZ + p0 + threadIdx.x] = tile[threadIdx.x][threadIdx.y + i * 8];
    }
}

// ---------------- LayerNorm over C=384, one warp per row ----------------
__global__ void ln_kernel(const float* __restrict__ in, float* __restrict__ out,
                          const float* __restrict__ g, const float* __restrict__ b) {
    const int row = blockIdx.x * 8 + threadIdx.y;
    const int lane = threadIdx.x;
    const float* xr = in + (size_t)row * CDIM;
    float v[12];
    float s = 0.f;
#pragma unroll
    for (int i = 0; i < 12; i++) { v[i] = xr[lane + i * 32]; s += v[i]; }
#pragma unroll
    for (int o = 16; o > 0; o >>= 1) s += __shfl_xor_sync(0xffffffffu, s, o);
    const float mean = s * (1.f / CDIM);
    float q = 0.f;
#pragma unroll
    for (int i = 0; i < 12; i++) { float d = v[i] - mean; q += d * d; }
#pragma unroll
    for (int o = 16; o > 0; o >>= 1) q += __shfl_xor_sync(0xffffffffu, q, o);
    const float r = rsqrtf(q * (1.f / CDIM) + 1e-5f);
    float* orow = out + (size_t)row * CDIM;
#pragma unroll
    for (int i = 0; i < 12; i++) {
        int c = lane + i * 32;
        orow[c] = (v[i] - mean) * r * g[c] + b[c];
    }
}

// ---------------- generic fp32 GEMM: C[M,N] = A[M,K]@B[K,N] (+bias)(+res+gamma) ----------------
// 128x128 block tile, BK=16, 256 threads, 8x8 micro-tile. All dims divide exactly.
__global__ __launch_bounds__(256) void gemm_kernel(
    const float* __restrict__ A, const float* __restrict__ B,
    const float* __restrict__ bias, const float* __restrict__ res,
    const float* __restrict__ gamma, float* __restrict__ C,
    int M, int N, int K)
{
    __shared__ float As[128][16];
    __shared__ float Bs[16][128];
    const int tid = threadIdx.x;
    const int bm = blockIdx.y * 128;
    const int bn = blockIdx.x * 128;
    const int tx = tid & 15;      // n direction
    const int ty = tid >> 4;      // m direction

    float acc[8][8];
#pragma unroll
    for (int i = 0; i < 8; i++)
#pragma unroll
        for (int j = 0; j < 8; j++) acc[i][j] = 0.f;

    for (int k0 = 0; k0 < K; k0 += 16) {
        // load A tile 128x16 as float4 (As[m][k] layout)
#pragma unroll
        for (int i = 0; i < 2; i++) {
            int f4 = tid + i * 256;                 // 0..511
            int mm = f4 >> 2, kq = (f4 & 3) * 4;
            *(float4*)&As[mm][kq] =
                *(const float4*)&A[(size_t)(bm + mm) * K + k0 + kq];
        }
        // load B tile 16x128 as float4
#pragma unroll
        for (int i = 0; i < 2; i++) {
            int f4 = tid + i * 256;
            int kk = f4 >> 5, nq = (f4 & 31) * 4;
            *(float4*)&Bs[kk][nq] =
                *(const float4*)&B[(size_t)(k0 + kk) * N + bn + nq];
        }
        __syncthreads();
#pragma unroll
        for (int k = 0; k < 16; k++) {
            float a[8], bb[8];
#pragma unroll
            for (int i = 0; i < 8; i++) a[i] = As[ty * 8 + i][k];
            float4 b0 = *(float4*)&Bs[k][tx * 8];
            float4 b1 = *(float4*)&Bs[k][tx * 8 + 4];
            bb[0] = b0.x; bb[1] = b0.y; bb[2] = b0.z; bb[3] = b0.w;
            bb[4] = b1.x; bb[5] = b1.y; bb[6] = b1.z; bb[7] = b1.w;
#pragma unroll
            for (int i = 0; i < 8; i++)
#pragma unroll
                for (int j = 0; j < 8; j++)
                    acc[i][j] = fmaf(a[i], bb[j], acc[i][j]);
        }
        __syncthreads();
    }

    // epilogue
    float bs[8], gs[8];
#pragma unroll
    for (int j = 0; j < 8; j++) {
        int n = bn + tx * 8 + j;
        bs[j] = bias ? bias[n] : 0.f;
        gs[j] = gamma ? gamma[n] : 1.f;
    }
#pragma unroll
    for (int i = 0; i < 8; i++) {
        size_t base = (size_t)(bm + ty * 8 + i) * N + bn + tx * 8;
#pragma unroll
        for (int jq = 0; jq < 2; jq++) {
            float4 v;
            float* vp = &v.x;
#pragma unroll
            for (int j = 0; j < 4; j++) vp[j] = acc[i][jq * 4 + j] + bs[jq * 4 + j];
            if (res) {
                float4 r4 = *(const float4*)&res[base + jq * 4];
                v.x = r4.x + gs[jq * 4 + 0] * v.x;
                v.y = r4.y + gs[jq * 4 + 1] * v.y;
                v.z = r4.z + gs[jq * 4 + 2] * v.z;
                v.w = r4.w + gs[jq * 4 + 3] * v.w;
            }
            *(float4*)&C[base + jq * 4] = v;
        }
    }
}

// ---------------- attention: one block per (window, head), 64 threads ----------------
__global__ __launch_bounds__(64) void attn_kernel(const float* __restrict__ qkv,
                                                  float* __restrict__ o) {
    __shared__ float sk[64][49];
    __shared__ float sv[64][49];
    __shared__ float ss[64][65];
    __shared__ int   srow[64];

    const int wnd  = blockIdx.x;            // 0..1567
    const int head = blockIdx.y;            // 0..7
    const int b  = wnd / (GSZ * GSZ);
    const int gy = (wnd / GSZ) % GSZ;
    const int gx = wnd % GSZ;
    const int tid = threadIdx.x;

    {   // token rows of this window
        int sy = tid / SPR, sx = tid % SPR;
        srow[tid] = b * HWSZ + (sy * GSZ + gy) * HDIM + (sx * GSZ + gx);
    }
    __syncthreads();

    // load K, V for the 64 tokens of this head
    for (int i = tid; i < 64 * HD; i += 64) {
        int t = i / HD, d = i % HD;
        size_t base = (size_t)srow[t] * (3 * CDIM) + head * HD + d;
        sk[t][d] = qkv[base + CDIM];
        sv[t][d] = qkv[base + 2 * CDIM];
    }
    __syncthreads();

    // per-thread query (pre-scaled)
    const float scale = 0.14433756729740643f;   // 1/sqrt(48)
    const float* qp = qkv + (size_t)srow[tid] * (3 * CDIM) + head * HD;
    float q[HD];
#pragma unroll
    for (int d = 0; d < HD; d++) q[d] = qp[d] * scale;

    // scores
    for (int j = 0; j < 64; j++) {
        float acc = 0.f;
#pragma unroll
        for (int d = 0; d < HD; d++) acc = fmaf(q[d], sk[j][d], acc);
        ss[tid][j] = acc;
    }
    // softmax (own row)
    float mx = -1e30f;
    for (int j = 0; j < 64; j++) mx = fmaxf(mx, ss[tid][j]);
    float sum = 0.f;
    for (int j = 0; j < 64; j++) {
        float p = expf(ss[tid][j] - mx);
        ss[tid][j] = p;
        sum += p;
    }
    const float inv = 1.f / sum;

    // o = attn @ V
    float oacc[HD];
#pragma unroll
    for (int d = 0; d < HD; d++) oacc[d] = 0.f;
    for (int j = 0; j < 64; j++) {
        float p = ss[tid][j];
#pragma unroll
        for (int d = 0; d < HD; d++) oacc[d] = fmaf(p, sv[j][d], oacc[d]);
    }
    float* op = o + (size_t)srow[tid] * CDIM + head * HD;
#pragma unroll
    for (int d = 0; d < HD; d++) op[d] = oacc[d] * inv;
}

// ---------------- depthwise 3x3 conv + bias + exact GELU ----------------
__global__ void dwconv_gelu_kernel(const float* __restrict__ m, const float* __restrict__ w,
                                   const float* __restrict__ bias, float* __restrict__ out) {
    const int bn = blockIdx.x;                        // 0..NTOK-1
    const int c  = blockIdx.y * 256 + threadIdx.x;    // 0..1535
    const int b  = bn / HWSZ;
    const int p  = bn % HWSZ;
    const int y  = p / HDIM;
    const int x  = p % HDIM;

    float wc[9];
#pragma unroll
    for (int i = 0; i < 9; i++) wc[i] = w[c * 9 + i];

    float acc = bias[c];
#pragma unroll
    for (int ky = 0; ky < 3; ky++) {
        int yy = y + ky - 1;
        if (yy < 0 || yy >= HDIM) continue;
#pragma unroll
        for (int kx = 0; kx < 3; kx++) {
            int xx = x + kx - 1;
            if (xx < 0 || xx >= HDIM) continue;
            acc = fmaf(m[((size_t)b * HWSZ + yy * HDIM + xx) * HID + c], wc[ky * 3 + kx], acc);
        }
    }
    // exact GELU: 0.5*x*(1+erf(x/sqrt(2)))
    float gl = 0.5f * acc * (1.f + erff(acc * 0.70710678118654752f));
    out[(size_t)bn * HID + c] = gl;
}

// ---------------- launch ----------------
extern "C" void kernel_launch(void* const* d_in, const int* in_sizes, int n_in,
                              void* d_out, int out_size) {
    const float* x      = (const float*)d_in[0];
    const float* ln1_g  = (const float*)d_in[1];
    const float* ln1_b  = (const float*)d_in[2];
    const float* qkv_w  = (const float*)d_in[3];
    const float* proj_w = (const float*)d_in[4];
    const float* proj_b = (const float*)d_in[5];
    const float* ln2_g  = (const float*)d_in[6];
    const float* ln2_b  = (const float*)d_in[7];
    const float* fc1_w  = (const float*)d_in[8];
    const float* fc1_b  = (const float*)d_in[9];
    const float* dw_w   = (const float*)d_in[10];
    const float* dw_b   = (const float*)d_in[11];
    const float* fc2_w  = (const float*)d_in[12];
    const float* fc2_b  = (const float*)d_in[13];
    const float* gamma1 = (const float*)d_in[14];
    const float* gamma2 = (const float*)d_in[15];
    float* out = (float*)d_out;

    float *xt, *h, *qkv, *m, *mg;
    cudaGetSymbolAddress((void**)&xt,  g_xt);
    cudaGetSymbolAddress((void**)&h,   g_h);
    cudaGetSymbolAddress((void**)&qkv, g_qkv);
    cudaGetSymbolAddress((void**)&m,   g_m);
    cudaGetSymbolAddress((void**)&mg,  g_mg);

    dim3 tb32x8(32, 8);

    // 1) x -> token-major
    transpose_in_kernel<<<dim3(HWSZ / 32, CDIM / 32, BATCH), tb32x8>>>(x, xt);
    // 2) LN1
    ln_kernel<<<NTOK / 8, tb32x8>>>(xt, h, ln1_g, ln1_b);
    // 3) qkv GEMM  [NTOK,384] @ [384,1152]
    gemm_kernel<<<dim3(1152 / 128, NTOK / 128), 256>>>(h, qkv_w, nullptr, nullptr, nullptr,
                                                       qkv, NTOK, 1152, CDIM);
    // 4) windowed attention -> h
    attn_kernel<<<dim3(BATCH * GSZ * GSZ, HEADS), 64>>>(qkv, h);
    // 5) proj GEMM + residual: xt = xt + gamma1*(h@proj_w + proj_b)   (in-place safe)
    gemm_kernel<<<dim3(CDIM / 128, NTOK / 128), 256>>>(h, proj_w, proj_b, xt, gamma1,
                                                       xt, NTOK, CDIM, CDIM);
    // 6) LN2
    ln_kernel<<<NTOK / 8, tb32x8>>>(xt, h, ln2_g, ln2_b);
    // 7) fc1 GEMM  [NTOK,384] @ [384,1536]
    gemm_kernel<<<dim3(HID / 128, NTOK / 128), 256>>>(h, fc1_w, fc1_b, nullptr, nullptr,
                                                      m, NTOK, HID, CDIM);
    // 8) depthwise conv + GELU
    dwconv_gelu_kernel<<<dim3(NTOK, HID / 256), 256>>>(m, dw_w, dw_b, mg);
    // 9) fc2 GEMM + residual: xt = xt + gamma2*(mg@fc2_w + fc2_b)
    gemm_kernel<<<dim3(CDIM / 128, NTOK / 128), 256>>>(mg, fc2_w, fc2_b, xt, gamma2,
                                                       xt, NTOK, CDIM, HID);
    // 10) token-major -> out[B,C,H,W]
    transpose_out_kernel<<<dim3(HWSZ / 32, CDIM / 32, BATCH), tb32x8>>>(xt, out);
}

// round 3
// speedup vs baseline: 2.6798x; 2.6798x over previous
#include <cuda_runtime.h>
#include <cuda_bf16.h>
#include <cstdint>
#include <math.h>

#define BATCH 32
#define CDIM  384
#define HDIM  56
#define HWSZ  3136          // 56*56
#define NTOK  100352        // BATCH*HWSZ
#define HID   1536
#define HEADS 8
#define HD    48
#define GSZ   7
#define SPR   8

typedef __nv_bfloat16 bf16;

// ---------------- scratch ----------------
__device__ float g_xt  [(size_t)NTOK * CDIM];        // fp32 residual path (x -> x1 -> x2)
__device__ bf16  g_hb  [(size_t)NTOK * CDIM];        // LN out / attn out (bf16)
__device__ bf16  g_qkvb[(size_t)NTOK * 3 * CDIM];    // qkv bf16
__device__ bf16  g_mb  [(size_t)NTOK * HID];         // fc1 out bf16
__device__ bf16  g_mgb [(size_t)NTOK * HID];         // dwconv+gelu out bf16
__device__ bf16  g_wqkv [3 * CDIM * CDIM];           // [1152][384]  (N-major, K contig)
__device__ bf16  g_wproj[CDIM * CDIM];               // [384][384]
__device__ bf16  g_wfc1 [HID * CDIM];                // [1536][384]
__device__ bf16  g_wfc2 [CDIM * HID];                // [384][1536]

// ---------------- weight transpose+convert: w[K][N] f32 -> o[N][K] bf16 ----------------
__global__ void wconv_kernel(const float* __restrict__ w, bf16* __restrict__ o, int K, int N) {
    __shared__ float tile[32][33];
    const int n0 = blockIdx.x * 32, k0 = blockIdx.y * 32;
#pragma unroll
    for (int i = 0; i < 4; i++)
        tile[threadIdx.y + i * 8][threadIdx.x] =
            w[(size_t)(k0 + threadIdx.y + i * 8) * N + n0 + threadIdx.x];
    __syncthreads();
#pragma unroll
    for (int i = 0; i < 4; i++)
        o[(size_t)(n0 + threadIdx.y + i * 8) * K + k0 + threadIdx.x] =
            __float2bfloat16(tile[threadIdx.x][threadIdx.y + i * 8]);
}

// ---------------- transpose in: x[B,C,HW] -> xt[B*HW, C] fp32 ----------------
__global__ void transpose_in_kernel(const float* __restrict__ x, float* __restrict__ xt) {
    __shared__ float tile[32][33];
    const int b = blockIdx.z, p0 = blockIdx.x * 32, c0 = blockIdx.y * 32;
    const float* xb = x + (size_t)b * CDIM * HWSZ;
#pragma unroll
    for (int i = 0; i < 4; i++)
        tile[threadIdx.y + i * 8][threadIdx.x] =
            xb[(size_t)(c0 + threadIdx.y + i * 8) * HWSZ + p0 + threadIdx.x];
    __syncthreads();
#pragma unroll
    for (int i = 0; i < 4; i++)
        xt[((size_t)b * HWSZ + p0 + threadIdx.y + i * 8) * CDIM + c0 + threadIdx.x] =
            tile[threadIdx.x][threadIdx.y + i * 8];
}

__global__ void transpose_out_kernel(const float* __restrict__ xt, float* __restrict__ out) {
    __shared__ float tile[32][33];
    const int b = blockIdx.z, p0 = blockIdx.x * 32, c0 = blockIdx.y * 32;
#pragma unroll
    for (int i = 0; i < 4; i++)
        tile[threadIdx.y + i * 8][threadIdx.x] =
            xt[((size_t)b * HWSZ + p0 + threadIdx.y + i * 8) * CDIM + c0 + threadIdx.x];
    __syncthreads();
    float* ob = out + (size_t)b * CDIM * HWSZ;
#pragma unroll
    for (int i = 0; i < 4; i++)
        ob[(size_t)(c0 + threadIdx.y + i * 8) * HWSZ + p0 + threadIdx.x] =
            tile[threadIdx.x][threadIdx.y + i * 8];
}

// ---------------- LayerNorm over C=384 (fp32 in, bf16 out), warp per row ----------------
__global__ void ln_kernel(const float* __restrict__ in, bf16* __restrict__ out,
                          const float* __restrict__ g, const float* __restrict__ b) {
    const int row = blockIdx.x * 8 + threadIdx.y;
    const int lane = threadIdx.x;
    const float* xr = in + (size_t)row * CDIM;
    float v[12];
    float s = 0.f;
#pragma unroll
    for (int i = 0; i < 12; i++) { v[i] = xr[lane + i * 32]; s += v[i]; }
#pragma unroll
    for (int o = 16; o > 0; o >>= 1) s += __shfl_xor_sync(0xffffffffu, s, o);
    const float mean = s * (1.f / CDIM);
    float q = 0.f;
#pragma unroll
    for (int i = 0; i < 12; i++) { float d = v[i] - mean; q += d * d; }
#pragma unroll
    for (int o = 16; o > 0; o >>= 1) q += __shfl_xor_sync(0xffffffffu, q, o);
    const float r = rsqrtf(q * (1.f / CDIM) + 1e-5f);
    bf16* orow = out + (size_t)row * CDIM;
#pragma unroll
    for (int i = 0; i < 12; i++) {
        int c = lane + i * 32;
        orow[c] = __float2bfloat16((v[i] - mean) * r * g[c] + b[c]);
    }
}

// ---------------- bf16 tensor-core GEMM ----------------
// C[M,N] = A[M,K] @ Bw^T   where A is [M][K] bf16 and Bw is [N][K] bf16 (pre-transposed).
// 128x128 tile, BK=32, 8 warps (warp tile 64x32), cp.async 2-stage, ldmatrix + mma.m16n8k16.
// EPI=0: bf16 out (+ optional bias).  EPI=1: fp32 out = res + gamma*(acc + bias).
#define PAD 40   // smem row stride in bf16 elems (80B -> conflict-free ldmatrix)

__device__ __forceinline__ unsigned int saddr(const void* p) {
    return (unsigned int)__cvta_generic_to_shared(p);
}

template<int EPI>
__global__ __launch_bounds__(256) void gemm_bf16_kernel(
    const bf16* __restrict__ A, const bf16* __restrict__ Bw,
    const float* __restrict__ bias, const float* __restrict__ res,
    const float* __restrict__ gamma, void* __restrict__ Cout,
    int M, int N, int K)
{
    __shared__ bf16 As[2][128 * PAD];
    __shared__ bf16 Bs[2][128 * PAD];

    const int tid  = threadIdx.x;
    const int lane = tid & 31;
    const int warp = tid >> 5;
    const int wm   = (warp >> 2) * 64;   // warp m offset in tile
    const int wn   = (warp & 3) * 32;    // warp n offset in tile
    const int bm   = blockIdx.y * 128;
    const int bn   = blockIdx.x * 128;

    float acc[4][4][4];
#pragma unroll
    for (int i = 0; i < 4; i++)
#pragma unroll
        for (int j = 0; j < 4; j++)
#pragma unroll
            for (int r = 0; r < 4; r++) acc[i][j][r] = 0.f;

    // ldmatrix per-lane offsets
    const int a_row = lane & 15;          // row within 16-row m-tile
    const int a_koff = (lane >> 4) * 8;   // k quadrant
    const int b_nrow = ((lane >> 4) * 8) + (lane & 7);  // n within 16-n pair
    const int b_koff = ((lane >> 3) & 1) * 8;

    const int iters = K / 32;

    // stage loader: 8-byte cp.async chunks (80B rows keep only 8B alignment)
    auto load_stage = [&](int s, int k0) {
#pragma unroll
        for (int i = 0; i < 4; i++) {
            int id = tid + i * 256;            // 0..1023
            int row = id >> 3, c4 = id & 7;    // 8 chunks of 4 bf16 per row
            const bf16* src = A + (size_t)(bm + row) * K + k0 + c4 * 4;
            unsigned int dst = saddr(&As[s][row * PAD + c4 * 4]);
            asm volatile("cp.async.ca.shared.global [%0], [%1], 8;" :: "r"(dst), "l"(src));
        }
#pragma unroll
        for (int i = 0; i < 4; i++) {
            int id = tid + i * 256;
            int row = id >> 3, c4 = id & 7;
            const bf16* src = Bw + (size_t)(bn + row) * K + k0 + c4 * 4;
            unsigned int dst = saddr(&Bs[s][row * PAD + c4 * 4]);
            asm volatile("cp.async.ca.shared.global [%0], [%1], 8;" :: "r"(dst), "l"(src));
        }
        asm volatile("cp.async.commit_group;");
    };

    load_stage(0, 0);

    for (int it = 0; it < iters; it++) {
        asm volatile("cp.async.wait_group 0;" ::: "memory");
        __syncthreads();
        if (it + 1 < iters) load_stage((it + 1) & 1, (it + 1) * 32);

        const bf16* as = As[it & 1];
        const bf16* bs = Bs[it & 1];

#pragma unroll
        for (int ks = 0; ks < 2; ks++) {
            unsigned int a[4][4];
#pragma unroll
            for (int i = 0; i < 4; i++) {
                unsigned int ad = saddr(&as[(wm + i * 16 + a_row) * PAD + ks * 16 + a_koff]);
                asm volatile("ldmatrix.sync.aligned.m8n8.x4.shared.b16 {%0,%1,%2,%3}, [%4];"
                             : "=r"(a[i][0]), "=r"(a[i][1]), "=r"(a[i][2]), "=r"(a[i][3])
                             : "r"(ad));
            }
            unsigned int b[4][2];
#pragma unroll
            for (int j2 = 0; j2 < 2; j2++) {
                unsigned int bd = saddr(&bs[(wn + j2 * 16 + b_nrow) * PAD + ks * 16 + b_koff]);
                unsigned int r0, r1, r2, r3;
                asm volatile("ldmatrix.sync.aligned.m8n8.x4.shared.b16 {%0,%1,%2,%3}, [%4];"
                             : "=r"(r0), "=r"(r1), "=r"(r2), "=r"(r3) : "r"(bd));
                b[j2 * 2 + 0][0] = r0; b[j2 * 2 + 0][1] = r1;
                b[j2 * 2 + 1][0] = r2; b[j2 * 2 + 1][1] = r3;
            }
#pragma unroll
            for (int i = 0; i < 4; i++)
#pragma unroll
                for (int j = 0; j < 4; j++)
                    asm volatile(
                        "mma.sync.aligned.m16n8k16.row.col.f32.bf16.bf16.f32 "
                        "{%0,%1,%2,%3}, {%4,%5,%6,%7}, {%8,%9}, {%0,%1,%2,%3};"
                        : "+f"(acc[i][j][0]), "+f"(acc[i][j][1]),
                          "+f"(acc[i][j][2]), "+f"(acc[i][j][3])
                        : "r"(a[i][0]), "r"(a[i][1]), "r"(a[i][2]), "r"(a[i][3]),
                          "r"(b[j][0]), "r"(b[j][1]));
        }
        __syncthreads();
    }

    // -------- epilogue --------
    const int rbase = bm + wm + (lane >> 2);
    const int cbase = bn + wn + (lane & 3) * 2;
#pragma unroll
    for (int j = 0; j < 4; j++) {
        const int c = cbase + j * 8;
        const float b0 = bias ? bias[c] : 0.f;
        const float b1 = bias ? bias[c + 1] : 0.f;
        float g0 = 1.f, g1 = 1.f;
        if (EPI == 1) { g0 = gamma[c]; g1 = gamma[c + 1]; }
#pragma unroll
        for (int i = 0; i < 4; i++) {
            const int r0 = rbase + i * 16;
#pragma unroll
            for (int h = 0; h < 2; h++) {
                const int r = r0 + h * 8;
                const float v0 = acc[i][j][h * 2 + 0] + b0;
                const float v1 = acc[i][j][h * 2 + 1] + b1;
                if (EPI == 0) {
                    bf16* C = (bf16*)Cout;
                    __nv_bfloat162 pv;
                    pv.x = __float2bfloat16(v0);
                    pv.y = __float2bfloat16(v1);
                    *(__nv_bfloat162*)&C[(size_t)r * N + c] = pv;
                } else {
                    float* C = (float*)Cout;
                    float2 rr = *(const float2*)&res[(size_t)r * N + c];
                    float2 o;
                    o.x = rr.x + g0 * v0;
                    o.y = rr.y + g1 * v1;
                    *(float2*)&C[(size_t)r * N + c] = o;
                }
            }
        }
    }
}

// ---------------- attention: one block per (window, head), bf16 qkv ----------------
__global__ __launch_bounds__(64) void attn_kernel(const bf16* __restrict__ qkv,
                                                  bf16* __restrict__ o) {
    __shared__ float sk[64][49];
    __shared__ float sv[64][49];
    __shared__ float ss[64][65];
    __shared__ int   srow[64];

    const int wnd  = blockIdx.x;
    const int head = blockIdx.y;
    const int b  = wnd / (GSZ * GSZ);
    const int gy = (wnd / GSZ) % GSZ;
    const int gx = wnd % GSZ;
    const int tid = threadIdx.x;

    {
        int sy = tid / SPR, sx = tid % SPR;
        srow[tid] = b * HWSZ + (sy * GSZ + gy) * HDIM + (sx * GSZ + gx);
    }
    __syncthreads();

    for (int i = tid; i < 64 * HD; i += 64) {
        int t = i / HD, d = i % HD;
        size_t base = (size_t)srow[t] * (3 * CDIM) + head * HD + d;
        sk[t][d] = __bfloat162float(qkv[base + CDIM]);
        sv[t][d] = __bfloat162float(qkv[base + 2 * CDIM]);
    }
    __syncthreads();

    const float scale = 0.14433756729740643f;   // 1/sqrt(48)
    const bf16* qp = qkv + (size_t)srow[tid] * (3 * CDIM) + head * HD;
    float q[HD];
#pragma unroll
    for (int d = 0; d < HD; d++) q[d] = __bfloat162float(qp[d]) * scale;

    for (int j = 0; j < 64; j++) {
        float a = 0.f;
#pragma unroll
        for (int d = 0; d < HD; d++) a = fmaf(q[d], sk[j][d], a);
        ss[tid][j] = a;
    }
    float mx = -1e30f;
    for (int j = 0; j < 64; j++) mx = fmaxf(mx, ss[tid][j]);
    float sum = 0.f;
    for (int j = 0; j < 64; j++) {
        float p = expf(ss[tid][j] - mx);
        ss[tid][j] = p; sum += p;
    }
    const float inv = 1.f / sum;

    float oacc[HD];
#pragma unroll
    for (int d = 0; d < HD; d++) oacc[d] = 0.f;
    for (int j = 0; j < 64; j++) {
        float p = ss[tid][j];
#pragma unroll
        for (int d = 0; d < HD; d++) oacc[d] = fmaf(p, sv[j][d], oacc[d]);
    }
    bf16* op = o + (size_t)srow[tid] * CDIM + head * HD;
#pragma unroll
    for (int d = 0; d < HD; d++) op[d] = __float2bfloat16(oacc[d] * inv);
}

// ---------------- depthwise 3x3 + bias + exact GELU (bf16 in/out, 2 ch/thread) ----------------
__global__ void dwconv_gelu_kernel(const bf16* __restrict__ m, const float* __restrict__ w,
                                   const float* __restrict__ bias, bf16* __restrict__ out) {
    const int bn = blockIdx.x;                              // token
    const int c  = (blockIdx.y * 256 + threadIdx.x) * 2;    // channel pair
    const int b  = bn / HWSZ;
    const int p  = bn % HWSZ;
    const int y  = p / HDIM;
    const int x  = p % HDIM;

    float w0[9], w1[9];
#pragma unroll
    for (int i = 0; i < 9; i++) { w0[i] = w[c * 9 + i]; w1[i] = w[(c + 1) * 9 + i]; }

    float a0 = bias[c], a1 = bias[c + 1];
#pragma unroll
    for (int ky = 0; ky < 3; ky++) {
        int yy = y + ky - 1;
        if (yy < 0 || yy >= HDIM) continue;
#pragma unroll
        for (int kx = 0; kx < 3; kx++) {
            int xx = x + kx - 1;
            if (xx < 0 || xx >= HDIM) continue;
            __nv_bfloat162 v = *(const __nv_bfloat162*)
                &m[((size_t)b * HWSZ + yy * HDIM + xx) * HID + c];
            a0 = fmaf(__bfloat162float(v.x), w0[ky * 3 + kx], a0);
            a1 = fmaf(__bfloat162float(v.y), w1[ky * 3 + kx], a1);
        }
    }
    const float k = 0.70710678118654752f;
    float gl0 = 0.5f * a0 * (1.f + erff(a0 * k));
    float gl1 = 0.5f * a1 * (1.f + erff(a1 * k));
    __nv_bfloat162 ov;
    ov.x = __float2bfloat16(gl0);
    ov.y = __float2bfloat16(gl1);
    *(__nv_bfloat162*)&out[(size_t)bn * HID + c] = ov;
}

// ---------------- launch ----------------
extern "C" void kernel_launch(void* const* d_in, const int* in_sizes, int n_in,
                              void* d_out, int out_size) {
    const float* x      = (const float*)d_in[0];
    const float* ln1_g  = (const float*)d_in[1];
    const float* ln1_b  = (const float*)d_in[2];
    const float* qkv_w  = (const float*)d_in[3];
    const float* proj_w = (const float*)d_in[4];
    const float* proj_b = (const float*)d_in[5];
    const float* ln2_g  = (const float*)d_in[6];
    const float* ln2_b  = (const float*)d_in[7];
    const float* fc1_w  = (const float*)d_in[8];
    const float* fc1_b  = (const float*)d_in[9];
    const float* dw_w   = (const float*)d_in[10];
    const float* dw_b   = (const float*)d_in[11];
    const float* fc2_w  = (const float*)d_in[12];
    const float* fc2_b  = (const float*)d_in[13];
    const float* gamma1 = (const float*)d_in[14];
    const float* gamma2 = (const float*)d_in[15];
    float* out = (float*)d_out;

    float *xt; bf16 *hb, *qkvb, *mb, *mgb, *wqkv, *wproj, *wfc1, *wfc2;
    cudaGetSymbolAddress((void**)&xt,   g_xt);
    cudaGetSymbolAddress((void**)&hb,   g_hb);
    cudaGetSymbolAddress((void**)&qkvb, g_qkvb);
    cudaGetSymbolAddress((void**)&mb,   g_mb);
    cudaGetSymbolAddress((void**)&mgb,  g_mgb);
    cudaGetSymbolAddress((void**)&wqkv, g_wqkv);
    cudaGetSymbolAddress((void**)&wproj,g_wproj);
    cudaGetSymbolAddress((void**)&wfc1, g_wfc1);
    cudaGetSymbolAddress((void**)&wfc2, g_wfc2);

    dim3 tb32x8(32, 8);

    // weight transpose+convert (tiny)
    wconv_kernel<<<dim3(1152 / 32, CDIM / 32), tb32x8>>>(qkv_w,  wqkv,  CDIM, 1152);
    wconv_kernel<<<dim3(CDIM / 32, CDIM / 32), tb32x8>>>(proj_w, wproj, CDIM, CDIM);
    wconv_kernel<<<dim3(HID  / 32, CDIM / 32), tb32x8>>>(fc1_w,  wfc1,  CDIM, HID);
    wconv_kernel<<<dim3(CDIM / 32, HID  / 32), tb32x8>>>(fc2_w,  wfc2,  HID,  CDIM);

    // 1) x -> token-major fp32
    transpose_in_kernel<<<dim3(HWSZ / 32, CDIM / 32, BATCH), tb32x8>>>(x, xt);
    // 2) LN1 -> bf16
    ln_kernel<<<NTOK / 8, tb32x8>>>(xt, hb, ln1_g, ln1_b);
    // 3) qkv GEMM  [NTOK,384]x[384,1152] -> bf16
    gemm_bf16_kernel<0><<<dim3(1152 / 128, NTOK / 128), 256>>>(
        hb, wqkv, nullptr, nullptr, nullptr, qkvb, NTOK, 1152, CDIM);
    // 4) windowed attention -> hb (bf16)
    attn_kernel<<<dim3(BATCH * GSZ * GSZ, HEADS), 64>>>(qkvb, hb);
    // 5) proj GEMM + residual: xt = xt + gamma1*(hb@proj + b)
    gemm_bf16_kernel<1><<<dim3(CDIM / 128, NTOK / 128), 256>>>(
        hb, wproj, proj_b, xt, gamma1, xt, NTOK, CDIM, CDIM);
    // 6) LN2 -> bf16
    ln_kernel<<<NTOK / 8, tb32x8>>>(xt, hb, ln2_g, ln2_b);
    // 7) fc1 GEMM -> bf16
    gemm_bf16_kernel<0><<<dim3(HID / 128, NTOK / 128), 256>>>(
        hb, wfc1, fc1_b, nullptr, nullptr, mb, NTOK, HID, CDIM);
    // 8) depthwise conv + GELU (bf16)
    dwconv_gelu_kernel<<<dim3(NTOK, HID / 512), 256>>>(mb, dw_w, dw_b, mgb);
    // 9) fc2 GEMM + residual: xt = xt + gamma2*(mgb@fc2 + b)
    gemm_bf16_kernel<1><<<dim3(CDIM / 128, NTOK / 128), 256>>>(
        mgb, wfc2, fc2_b, xt, gamma2, xt, NTOK, CDIM, HID);
    // 10) out
    transpose_out_kernel<<<dim3(HWSZ / 32, CDIM / 32, BATCH), tb32x8>>>(xt, out);
}

// round 5
// speedup vs baseline: 2.9218x; 1.0903x over previous
#include <cuda_runtime.h>
#include <cuda_bf16.h>
#include <cstdint>
#include <math.h>

#define BATCH 32
#define CDIM  384
#define HDIM  56
#define HWSZ  3136
#define NTOK  100352
#define HID   1536
#define HEADS 8
#define HD    48
#define GSZ   7
#define SPR   8

typedef __nv_bfloat16 bf16;

// ---------------- scratch ----------------
__device__ float g_xt  [(size_t)NTOK * CDIM];
__device__ bf16  g_hb  [(size_t)NTOK * CDIM];
__device__ bf16  g_qkvb[(size_t)NTOK * 3 * CDIM];
__device__ bf16  g_mb  [(size_t)NTOK * HID];
__device__ bf16  g_mgb [(size_t)NTOK * HID];
__device__ bf16  g_wqkv [3 * CDIM * CDIM];
__device__ bf16  g_wproj[CDIM * CDIM];
__device__ bf16  g_wfc1 [HID * CDIM];
__device__ bf16  g_wfc2 [CDIM * HID];

__device__ __forceinline__ unsigned int saddr(const void* p) {
    return (unsigned int)__cvta_generic_to_shared(p);
}
__device__ __forceinline__ void cp16(unsigned int dst, const void* src) {
    asm volatile("cp.async.cg.shared.global [%0], [%1], 16;" :: "r"(dst), "l"(src));
}

// ================== bf16 HMMA GEMM ==================
// C[M,N] = A[M,K] @ Bw^T, A=[M][K] bf16, Bw=[N][K] bf16.
// Block 128x128, 4 warps, warp tile 64x64, BK=32, 3-stage cp.async ring.
// EPI=0: bf16 out (+bias).  EPI=1: fp32 out = res + gamma*(acc+bias).
#define PAD 40          // bf16 elems per smem row (80B)
#define STG 3
#define TILE_ELE (128 * PAD)

template<int EPI>
__global__ __launch_bounds__(128) void gemm_bf16_kernel(
    const bf16* __restrict__ A, const bf16* __restrict__ Bw,
    const float* __restrict__ bias, const float* __restrict__ res,
    const float* __restrict__ gamma, void* __restrict__ Cout,
    int M, int N, int K)
{
    extern __shared__ bf16 sm[];
    bf16* As = sm;                       // [STG][128*PAD]
    bf16* Bs = sm + STG * TILE_ELE;      // [STG][128*PAD]

    const int tid  = threadIdx.x;
    const int lane = tid & 31;
    const int warp = tid >> 5;
    const int wm   = (warp >> 1) * 64;
    const int wn   = (warp & 1) * 64;
    const int bm   = blockIdx.y * 128;
    const int bn   = blockIdx.x * 128;

    float acc[4][8][4];
#pragma unroll
    for (int i = 0; i < 4; i++)
#pragma unroll
        for (int j = 0; j < 8; j++)
#pragma unroll
            for (int r = 0; r < 4; r++) acc[i][j][r] = 0.f;

    const int a_row  = lane & 15;
    const int a_koff = (lane >> 4) * 8;
    const int b_nrow = ((lane >> 4) * 8) + (lane & 7);
    const int b_koff = ((lane >> 3) & 1) * 8;

    const int iters = K / 32;

    // loader: 16B chunks; id = row*4 + c  (row 0..127, c 0..3)
    auto load_stage = [&](int s, int k0) {
        bf16* as = As + s * TILE_ELE;
        bf16* bs = Bs + s * TILE_ELE;
#pragma unroll
        for (int u = 0; u < 4; u++) {
            int id = u * 128 + tid;
            int row = id >> 2, c = id & 3;
            cp16(saddr(&as[row * PAD + c * 8]),
                 A + (size_t)(bm + row) * K + k0 + c * 8);
        }
#pragma unroll
        for (int u = 0; u < 4; u++) {
            int id = u * 128 + tid;
            int row = id >> 2, c = id & 3;
            cp16(saddr(&bs[row * PAD + c * 8]),
                 Bw + (size_t)(bn + row) * K + k0 + c * 8);
        }
    };

    load_stage(0, 0);
    asm volatile("cp.async.commit_group;");
    load_stage(1, 32);
    asm volatile("cp.async.commit_group;");
    asm volatile("cp.async.wait_group 1;" ::: "memory");
    __syncthreads();

    for (int it = 0; it < iters; it++) {
        if (it + 2 < iters) load_stage((it + 2) % STG, (it + 2) * 32);
        asm volatile("cp.async.commit_group;");

        const bf16* as = As + (it % STG) * TILE_ELE;
        const bf16* bs = Bs + (it % STG) * TILE_ELE;

#pragma unroll
        for (int ks = 0; ks < 2; ks++) {
            unsigned int a[4][4];
#pragma unroll
            for (int i = 0; i < 4; i++) {
                unsigned int ad = saddr(&as[(wm + i * 16 + a_row) * PAD + ks * 16 + a_koff]);
                asm volatile("ldmatrix.sync.aligned.m8n8.x4.shared.b16 {%0,%1,%2,%3}, [%4];"
                             : "=r"(a[i][0]), "=r"(a[i][1]), "=r"(a[i][2]), "=r"(a[i][3])
                             : "r"(ad));
            }
            unsigned int b[8][2];
#pragma unroll
            for (int j2 = 0; j2 < 4; j2++) {
                unsigned int bd = saddr(&bs[(wn + j2 * 16 + b_nrow) * PAD + ks * 16 + b_koff]);
                unsigned int r0, r1, r2, r3;
                asm volatile("ldmatrix.sync.aligned.m8n8.x4.shared.b16 {%0,%1,%2,%3}, [%4];"
                             : "=r"(r0), "=r"(r1), "=r"(r2), "=r"(r3) : "r"(bd));
                b[j2 * 2 + 0][0] = r0; b[j2 * 2 + 0][1] = r1;
                b[j2 * 2 + 1][0] = r2; b[j2 * 2 + 1][1] = r3;
            }
#pragma unroll
            for (int i = 0; i < 4; i++)
#pragma unroll
                for (int j = 0; j < 8; j++)
                    asm volatile(
                        "mma.sync.aligned.m16n8k16.row.col.f32.bf16.bf16.f32 "
                        "{%0,%1,%2,%3}, {%4,%5,%6,%7}, {%8,%9}, {%0,%1,%2,%3};"
                        : "+f"(acc[i][j][0]), "+f"(acc[i][j][1]),
                          "+f"(acc[i][j][2]), "+f"(acc[i][j][3])
                        : "r"(a[i][0]), "r"(a[i][1]), "r"(a[i][2]), "r"(a[i][3]),
                          "r"(b[j][0]), "r"(b[j][1]));
        }
        asm volatile("cp.async.wait_group 1;" ::: "memory");
        __syncthreads();
    }

    // -------- epilogue --------
    const int rbase = bm + wm + (lane >> 2);
    const int cbase = bn + wn + (lane & 3) * 2;
#pragma unroll
    for (int j = 0; j < 8; j++) {
        const int c = cbase + j * 8;
        const float b0 = bias ? bias[c] : 0.f;
        const float b1 = bias ? bias[c + 1] : 0.f;
        float g0 = 1.f, g1 = 1.f;
        if (EPI == 1) { g0 = gamma[c]; g1 = gamma[c + 1]; }
#pragma unroll
        for (int i = 0; i < 4; i++) {
#pragma unroll
            for (int h = 0; h < 2; h++) {
                const int r = rbase + i * 16 + h * 8;
                const float v0 = acc[i][j][h * 2 + 0] + b0;
                const float v1 = acc[i][j][h * 2 + 1] + b1;
                if (EPI == 0) {
                    bf16* C = (bf16*)Cout;
                    __nv_bfloat162 pv;
                    pv.x = __float2bfloat16(v0);
                    pv.y = __float2bfloat16(v1);
                    *(__nv_bfloat162*)&C[(size_t)r * N + c] = pv;
                } else {
                    float* C = (float*)Cout;
                    float2 rr = *(const float2*)&res[(size_t)r * N + c];
                    float2 o;
                    o.x = rr.x + g0 * v0;
                    o.y = rr.y + g1 * v1;
                    *(float2*)&C[(size_t)r * N + c] = o;
                }
            }
        }
    }
}
#define GEMM_SMEM (STG * 2 * TILE_ELE * (int)sizeof(bf16))

// ---------------- weight transpose+convert ----------------
__global__ void wconv_kernel(const float* __restrict__ w, bf16* __restrict__ o, int K, int N) {
    __shared__ float tile[32][33];
    const int n0 = blockIdx.x * 32, k0 = blockIdx.y * 32;
#pragma unroll
    for (int i = 0; i < 4; i++)
        tile[threadIdx.y + i * 8][threadIdx.x] =
            w[(size_t)(k0 + threadIdx.y + i * 8) * N + n0 + threadIdx.x];
    __syncthreads();
#pragma unroll
    for (int i = 0; i < 4; i++)
        o[(size_t)(n0 + threadIdx.y + i * 8) * K + k0 + threadIdx.x] =
            __float2bfloat16(tile[threadIdx.x][threadIdx.y + i * 8]);
}

// ---------------- transposes ----------------
__global__ void transpose_in_kernel(const float* __restrict__ x, float* __restrict__ xt) {
    __shared__ float tile[32][33];
    const int b = blockIdx.z, p0 = blockIdx.x * 32, c0 = blockIdx.y * 32;
    const float* xb = x + (size_t)b * CDIM * HWSZ;
#pragma unroll
    for (int i = 0; i < 4; i++)
        tile[threadIdx.y + i * 8][threadIdx.x] =
            xb[(size_t)(c0 + threadIdx.y + i * 8) * HWSZ + p0 + threadIdx.x];
    __syncthreads();
#pragma unroll
    for (int i = 0; i < 4; i++)
        xt[((size_t)b * HWSZ + p0 + threadIdx.y + i * 8) * CDIM + c0 + threadIdx.x] =
            tile[threadIdx.x][threadIdx.y + i * 8];
}
__global__ void transpose_out_kernel(const float* __restrict__ xt, float* __restrict__ out) {
    __shared__ float tile[32][33];
    const int b = blockIdx.z, p0 = blockIdx.x * 32, c0 = blockIdx.y * 32;
#pragma unroll
    for (int i = 0; i < 4; i++)
        tile[threadIdx.y + i * 8][threadIdx.x] =
            xt[((size_t)b * HWSZ + p0 + threadIdx.y + i * 8) * CDIM + c0 + threadIdx.x];
    __syncthreads();
    float* ob = out + (size_t)b * CDIM * HWSZ;
#pragma unroll
    for (int i = 0; i < 4; i++)
        ob[(size_t)(c0 + threadIdx.y + i * 8) * HWSZ + p0 + threadIdx.x] =
            tile[threadIdx.x][threadIdx.y + i * 8];
}

// ---------------- LayerNorm (fp32 in, bf16 out) ----------------
__global__ void ln_kernel(const float* __restrict__ in, bf16* __restrict__ out,
                          const float* __restrict__ g, const float* __restrict__ b) {
    const int row = blockIdx.x * 8 + threadIdx.y;
    const int lane = threadIdx.x;
    const float* xr = in + (size_t)row * CDIM;
    float v[12];
    float s = 0.f;
#pragma unroll
    for (int i = 0; i < 12; i++) { v[i] = xr[lane + i * 32]; s += v[i]; }
#pragma unroll
    for (int o = 16; o > 0; o >>= 1) s += __shfl_xor_sync(0xffffffffu, s, o);
    const float mean = s * (1.f / CDIM);
    float q = 0.f;
#pragma unroll
    for (int i = 0; i < 12; i++) { float d = v[i] - mean; q += d * d; }
#pragma unroll
    for (int o = 16; o > 0; o >>= 1) q += __shfl_xor_sync(0xffffffffu, q, o);
    const float r = rsqrtf(q * (1.f / CDIM) + 1e-5f);
    bf16* orow = out + (size_t)row * CDIM;
#pragma unroll
    for (int i = 0; i < 12; i++) {
        int c = lane + i * 32;
        orow[c] = __float2bfloat16((v[i] - mean) * r * g[c] + b[c]);
    }
}

// ---------------- attention ----------------
__global__ __launch_bounds__(64) void attn_kernel(const bf16* __restrict__ qkv,
                                                  bf16* __restrict__ o) {
    __shared__ float sk[64][49];
    __shared__ float sv[64][49];
    __shared__ float ss[64][65];
    __shared__ int   srow[64];

    const int wnd  = blockIdx.x;
    const int head = blockIdx.y;
    const int b  = wnd / (GSZ * GSZ);
    const int gy = (wnd / GSZ) % GSZ;
    const int gx = wnd % GSZ;
    const int tid = threadIdx.x;
    {
        int sy = tid / SPR, sx = tid % SPR;
        srow[tid] = b * HWSZ + (sy * GSZ + gy) * HDIM + (sx * GSZ + gx);
    }
    __syncthreads();
    for (int i = tid; i < 64 * HD; i += 64) {
        int t = i / HD, d = i % HD;
        size_t base = (size_t)srow[t] * (3 * CDIM) + head * HD + d;
        sk[t][d] = __bfloat162float(qkv[base + CDIM]);
        sv[t][d] = __bfloat162float(qkv[base + 2 * CDIM]);
    }
    __syncthreads();
    const float scale = 0.14433756729740643f;
    const bf16* qp = qkv + (size_t)srow[tid] * (3 * CDIM) + head * HD;
    float q[HD];
#pragma unroll
    for (int d = 0; d < HD; d++) q[d] = __bfloat162float(qp[d]) * scale;
    for (int j = 0; j < 64; j++) {
        float a = 0.f;
#pragma unroll
        for (int d = 0; d < HD; d++) a = fmaf(q[d], sk[j][d], a);
        ss[tid][j] = a;
    }
    float mx = -1e30f;
    for (int j = 0; j < 64; j++) mx = fmaxf(mx, ss[tid][j]);
    float sum = 0.f;
    for (int j = 0; j < 64; j++) {
        float p = expf(ss[tid][j] - mx);
        ss[tid][j] = p; sum += p;
    }
    const float inv = 1.f / sum;
    float oacc[HD];
#pragma unroll
    for (int d = 0; d < HD; d++) oacc[d] = 0.f;
    for (int j = 0; j < 64; j++) {
        float p = ss[tid][j];
#pragma unroll
        for (int d = 0; d < HD; d++) oacc[d] = fmaf(p, sv[j][d], oacc[d]);
    }
    bf16* op = o + (size_t)srow[tid] * CDIM + head * HD;
#pragma unroll
    for (int d = 0; d < HD; d++) op[d] = __float2bfloat16(oacc[d] * inv);
}

// ---------------- depthwise 3x3 + bias + exact GELU ----------------
__global__ void dwconv_gelu_kernel(const bf16* __restrict__ m, const float* __restrict__ w,
                                   const float* __restrict__ bias, bf16* __restrict__ out) {
    const int bn = blockIdx.x;
    const int c  = (blockIdx.y * 256 + threadIdx.x) * 2;
    const int b  = bn / HWSZ;
    const int p  = bn % HWSZ;
    const int y  = p / HDIM;
    const int x  = p % HDIM;

    float w0[9], w1[9];
#pragma unroll
    for (int i = 0; i < 9; i++) { w0[i] = w[c * 9 + i]; w1[i] = w[(c + 1) * 9 + i]; }

    float a0 = bias[c], a1 = bias[c + 1];
#pragma unroll
    for (int ky = 0; ky < 3; ky++) {
        int yy = y + ky - 1;
        if (yy < 0 || yy >= HDIM) continue;
#pragma unroll
        for (int kx = 0; kx < 3; kx++) {
            int xx = x + kx - 1;
            if (xx < 0 || xx >= HDIM) continue;
            __nv_bfloat162 v = *(const __nv_bfloat162*)
                &m[((size_t)b * HWSZ + yy * HDIM + xx) * HID + c];
            a0 = fmaf(__bfloat162float(v.x), w0[ky * 3 + kx], a0);
            a1 = fmaf(__bfloat162float(v.y), w1[ky * 3 + kx], a1);
        }
    }
    const float k = 0.70710678118654752f;
    float gl0 = 0.5f * a0 * (1.f + erff(a0 * k));
    float gl1 = 0.5f * a1 * (1.f + erff(a1 * k));
    __nv_bfloat162 ov;
    ov.x = __float2bfloat16(gl0);
    ov.y = __float2bfloat16(gl1);
    *(__nv_bfloat162*)&out[(size_t)bn * HID + c] = ov;
}

// ---------------- launch ----------------
extern "C" void kernel_launch(void* const* d_in, const int* in_sizes, int n_in,
                              void* d_out, int out_size) {
    const float* x      = (const float*)d_in[0];
    const float* ln1_g  = (const float*)d_in[1];
    const float* ln1_b  = (const float*)d_in[2];
    const float* qkv_w  = (const float*)d_in[3];
    const float* proj_w = (const float*)d_in[4];
    const float* proj_b = (const float*)d_in[5];
    const float* ln2_g  = (const float*)d_in[6];
    const float* ln2_b  = (const float*)d_in[7];
    const float* fc1_w  = (const float*)d_in[8];
    const float* fc1_b  = (const float*)d_in[9];
    const float* dw_w   = (const float*)d_in[10];
    const float* dw_b   = (const float*)d_in[11];
    const float* fc2_w  = (const float*)d_in[12];
    const float* fc2_b  = (const float*)d_in[13];
    const float* gamma1 = (const float*)d_in[14];
    const float* gamma2 = (const float*)d_in[15];
    float* out = (float*)d_out;

    float *xt; bf16 *hb, *qkvb, *mb, *mgb, *wqkv, *wproj, *wfc1, *wfc2;
    cudaGetSymbolAddress((void**)&xt,   g_xt);
    cudaGetSymbolAddress((void**)&hb,   g_hb);
    cudaGetSymbolAddress((void**)&qkvb, g_qkvb);
    cudaGetSymbolAddress((void**)&mb,   g_mb);
    cudaGetSymbolAddress((void**)&mgb,  g_mgb);
    cudaGetSymbolAddress((void**)&wqkv, g_wqkv);
    cudaGetSymbolAddress((void**)&wproj,g_wproj);
    cudaGetSymbolAddress((void**)&wfc1, g_wfc1);
    cudaGetSymbolAddress((void**)&wfc2, g_wfc2);

    static bool attr_done = false;
    if (!attr_done) {
        cudaFuncSetAttribute(gemm_bf16_kernel<0>,
                             cudaFuncAttributeMaxDynamicSharedMemorySize, GEMM_SMEM);
        cudaFuncSetAttribute(gemm_bf16_kernel<1>,
                             cudaFuncAttributeMaxDynamicSharedMemorySize, GEMM_SMEM);
        attr_done = true;
    }

    dim3 tb32x8(32, 8);

    wconv_kernel<<<dim3(1152 / 32, CDIM / 32), tb32x8>>>(qkv_w,  wqkv,  CDIM, 1152);
    wconv_kernel<<<dim3(CDIM / 32, CDIM / 32), tb32x8>>>(proj_w, wproj, CDIM, CDIM);
    wconv_kernel<<<dim3(HID  / 32, CDIM / 32), tb32x8>>>(fc1_w,  wfc1,  CDIM, HID);
    wconv_kernel<<<dim3(CDIM / 32, HID  / 32), tb32x8>>>(fc2_w,  wfc2,  HID,  CDIM);

    transpose_in_kernel<<<dim3(HWSZ / 32, CDIM / 32, BATCH), tb32x8>>>(x, xt);
    ln_kernel<<<NTOK / 8, tb32x8>>>(xt, hb, ln1_g, ln1_b);

    gemm_bf16_kernel<0><<<dim3(1152 / 128, NTOK / 128), 128, GEMM_SMEM>>>(
        hb, wqkv, nullptr, nullptr, nullptr, qkvb, NTOK, 1152, CDIM);
    attn_kernel<<<dim3(BATCH * GSZ * GSZ, HEADS), 64>>>(qkvb, hb);
    gemm_bf16_kernel<1><<<dim3(CDIM / 128, NTOK / 128), 128, GEMM_SMEM>>>(
        hb, wproj, proj_b, xt, gamma1, xt, NTOK, CDIM, CDIM);
    ln_kernel<<<NTOK / 8, tb32x8>>>(xt, hb, ln2_g, ln2_b);
    gemm_bf16_kernel<0><<<dim3(HID / 128, NTOK / 128), 128, GEMM_SMEM>>>(
        hb, wfc1, fc1_b, nullptr, nullptr, mb, NTOK, HID, CDIM);
    dwconv_gelu_kernel<<<dim3(NTOK, HID / 512), 256>>>(mb, dw_w, dw_b, mgb);
    gemm_bf16_kernel<1><<<dim3(CDIM / 128, NTOK / 128), 128, GEMM_SMEM>>>(
        mgb, wfc2, fc2_b, xt, gamma2, xt, NTOK, CDIM, HID);

    transpose_out_kernel<<<dim3(HWSZ / 32, CDIM / 32, BATCH), tb32x8>>>(xt, out);
}

// round 6
// speedup vs baseline: 3.2230x; 1.1031x over previous
#include <cuda_runtime.h>
#include <cuda_bf16.h>
#include <cuda_fp8.h>
#include <cstdint>
#include <math.h>

#define BATCH 32
#define CDIM  384
#define HDIM  56
#define HWSZ  3136
#define NTOK  100352
#define HID   1536
#define HEADS 8
#define HD    48
#define GSZ   7
#define SPR   8

typedef __nv_bfloat16 bf16;
typedef __nv_fp8_e4m3 fp8;

#define WSCALE     64.0f
#define INV_WSCALE 0.015625f

// ---------------- scratch ----------------
__device__ float g_xt  [(size_t)NTOK * CDIM];        // fp32 residual path
__device__ fp8   g_h8  [(size_t)NTOK * CDIM];        // LN1 out / attn out / LN2 out (fp8)
__device__ bf16  g_qkvb[(size_t)NTOK * 3 * CDIM];    // qkv (bf16, read by attn)
__device__ bf16  g_mb  [(size_t)NTOK * HID];         // fc1 out (bf16, read by dwconv)
__device__ fp8   g_mg8 [(size_t)NTOK * HID];         // dwconv+gelu out (fp8)
__device__ fp8   g_wqkv8 [3 * CDIM * CDIM];          // weights fp8, [N][K], x64 scaled
__device__ fp8   g_wproj8[CDIM * CDIM];
__device__ fp8   g_wfc18 [HID * CDIM];
__device__ fp8   g_wfc28 [CDIM * HID];

__device__ __forceinline__ unsigned int saddr(const void* p) {
    return (unsigned int)__cvta_generic_to_shared(p);
}
__device__ __forceinline__ void cp16(unsigned int dst, const void* src) {
    asm volatile("cp.async.cg.shared.global [%0], [%1], 16;" :: "r"(dst), "l"(src));
}

// ================== FP8 e4m3 tensor-core GEMM ==================
// C[M,N] = (A[M,K] @ Bw^T) * INV_WSCALE, A=[M][K] fp8, Bw=[N][K] fp8 (x64-scaled).
// Block 128x128, 4 warps (warp tile 64x64), BK=64 (bytes), 3-stage cp.async ring.
// EPI=0: bf16 out (+bias).  EPI=1: fp32 out = res + gamma*(acc*inv+bias).
#define PADB 80            // bytes per smem row (64B data + 16B pad) — conflict-free 16B-chunk layout
#define STG 3
#define TILEB (128 * PADB) // 10240 B per stage per matrix

template<int EPI>
__global__ __launch_bounds__(128) void gemm_fp8_kernel(
    const fp8* __restrict__ A, const fp8* __restrict__ Bw,
    const float* __restrict__ bias, const float* __restrict__ res,
    const float* __restrict__ gamma, void* __restrict__ Cout,
    int M, int N, int K)
{
    extern __shared__ char sm8[];
    char* As = sm8;                       // [STG][TILEB]
    char* Bs = sm8 + STG * TILEB;

    const int tid  = threadIdx.x;
    const int lane = tid & 31;
    const int warp = tid >> 5;
    const int wm   = (warp >> 1) * 64;
    const int wn   = (warp & 1) * 64;
    const int bm   = blockIdx.y * 128;
    const int bn   = blockIdx.x * 128;

    float acc[4][8][4];
#pragma unroll
    for (int i = 0; i < 4; i++)
#pragma unroll
        for (int j = 0; j < 8; j++)
#pragma unroll
            for (int r = 0; r < 4; r++) acc[i][j][r] = 0.f;

    const int a_row  = lane & 15;
    const int a_kb   = (lane >> 4) * 16;          // byte offset within 32B k-half
    const int b_nrow = ((lane >> 4) * 8) + (lane & 7);
    const int b_kb   = ((lane >> 3) & 1) * 16;

    const int iters = K / 64;

    // loader: 16B chunks; row 0..127, 4 chunks of 16B per 64B row
    auto load_stage = [&](int s, int k0) {
        char* as = As + s * TILEB;
        char* bs = Bs + s * TILEB;
#pragma unroll
        for (int u = 0; u < 4; u++) {
            int id = u * 128 + tid;
            int row = id >> 2, c = id & 3;
            cp16(saddr(as + row * PADB + c * 16),
                 (const char*)A + (size_t)(bm + row) * K + k0 + c * 16);
        }
#pragma unroll
        for (int u = 0; u < 4; u++) {
            int id = u * 128 + tid;
            int row = id >> 2, c = id & 3;
            cp16(saddr(bs + row * PADB + c * 16),
                 (const char*)Bw + (size_t)(bn + row) * K + k0 + c * 16);
        }
    };

    load_stage(0, 0);
    asm volatile("cp.async.commit_group;");
    load_stage(1, 64);
    asm volatile("cp.async.commit_group;");
    asm volatile("cp.async.wait_group 1;" ::: "memory");
    __syncthreads();

    for (int it = 0; it < iters; it++) {
        if (it + 2 < iters) load_stage((it + 2) % STG, (it + 2) * 64);
        asm volatile("cp.async.commit_group;");

        const char* as = As + (it % STG) * TILEB;
        const char* bs = Bs + (it % STG) * TILEB;

#pragma unroll
        for (int ks = 0; ks < 2; ks++) {             // two k32 steps per BK=64
            unsigned int a[4][4];
#pragma unroll
            for (int i = 0; i < 4; i++) {
                unsigned int ad = saddr(as + (wm + i * 16 + a_row) * PADB + ks * 32 + a_kb);
                asm volatile("ldmatrix.sync.aligned.m8n8.x4.shared.b16 {%0,%1,%2,%3}, [%4];"
                             : "=r"(a[i][0]), "=r"(a[i][1]), "=r"(a[i][2]), "=r"(a[i][3])
                             : "r"(ad));
            }
            unsigned int b[8][2];
#pragma unroll
            for (int j2 = 0; j2 < 4; j2++) {
                unsigned int bd = saddr(bs + (wn + j2 * 16 + b_nrow) * PADB + ks * 32 + b_kb);
                unsigned int r0, r1, r2, r3;
                asm volatile("ldmatrix.sync.aligned.m8n8.x4.shared.b16 {%0,%1,%2,%3}, [%4];"
                             : "=r"(r0), "=r"(r1), "=r"(r2), "=r"(r3) : "r"(bd));
                b[j2 * 2 + 0][0] = r0; b[j2 * 2 + 0][1] = r1;
                b[j2 * 2 + 1][0] = r2; b[j2 * 2 + 1][1] = r3;
            }
#pragma unroll
            for (int i = 0; i < 4; i++)
#pragma unroll
                for (int j = 0; j < 8; j++)
                    asm volatile(
                        "mma.sync.aligned.m16n8k32.row.col.f32.e4m3.e4m3.f32 "
                        "{%0,%1,%2,%3}, {%4,%5,%6,%7}, {%8,%9}, {%0,%1,%2,%3};"
                        : "+f"(acc[i][j][0]), "+f"(acc[i][j][1]),
                          "+f"(acc[i][j][2]), "+f"(acc[i][j][3])
                        : "r"(a[i][0]), "r"(a[i][1]), "r"(a[i][2]), "r"(a[i][3]),
                          "r"(b[j][0]), "r"(b[j][1]));
        }
        asm volatile("cp.async.wait_group 1;" ::: "memory");
        __syncthreads();
    }

    // -------- epilogue (descale weights) --------
    const int rbase = bm + wm + (lane >> 2);
    const int cbase = bn + wn + (lane & 3) * 2;
#pragma unroll
    for (int j = 0; j < 8; j++) {
        const int c = cbase + j * 8;
        const float b0 = bias ? bias[c] : 0.f;
        const float b1 = bias ? bias[c + 1] : 0.f;
        float g0 = 1.f, g1 = 1.f;
        if (EPI == 1) { g0 = gamma[c]; g1 = gamma[c + 1]; }
#pragma unroll
        for (int i = 0; i < 4; i++) {
#pragma unroll
            for (int h = 0; h < 2; h++) {
                const int r = rbase + i * 16 + h * 8;
                const float v0 = acc[i][j][h * 2 + 0] * INV_WSCALE + b0;
                const float v1 = acc[i][j][h * 2 + 1] * INV_WSCALE + b1;
                if (EPI == 0) {
                    bf16* C = (bf16*)Cout;
                    __nv_bfloat162 pv;
                    pv.x = __float2bfloat16(v0);
                    pv.y = __float2bfloat16(v1);
                    *(__nv_bfloat162*)&C[(size_t)r * N + c] = pv;
                } else {
                    float* C = (float*)Cout;
                    float2 rr = *(const float2*)&res[(size_t)r * N + c];
                    float2 o;
                    o.x = rr.x + g0 * v0;
                    o.y = rr.y + g1 * v1;
                    *(float2*)&C[(size_t)r * N + c] = o;
                }
            }
        }
    }
}
#define GEMM_SMEM (STG * 2 * TILEB)

// ---------------- weight transpose+convert: w[K][N] f32 -> o[N][K] fp8 (x64) ----------------
__global__ void wconv_kernel(const float* __restrict__ w, fp8* __restrict__ o, int K, int N) {
    __shared__ float tile[32][33];
    const int n0 = blockIdx.x * 32, k0 = blockIdx.y * 32;
#pragma unroll
    for (int i = 0; i < 4; i++)
        tile[threadIdx.y + i * 8][threadIdx.x] =
            w[(size_t)(k0 + threadIdx.y + i * 8) * N + n0 + threadIdx.x];
    __syncthreads();
#pragma unroll
    for (int i = 0; i < 4; i++)
        o[(size_t)(n0 + threadIdx.y + i * 8) * K + k0 + threadIdx.x] =
            fp8(tile[threadIdx.x][threadIdx.y + i * 8] * WSCALE);
}

// ---------------- transposes ----------------
__global__ void transpose_in_kernel(const float* __restrict__ x, float* __restrict__ xt) {
    __shared__ float tile[32][33];
    const int b = blockIdx.z, p0 = blockIdx.x * 32, c0 = blockIdx.y * 32;
    const float* xb = x + (size_t)b * CDIM * HWSZ;
#pragma unroll
    for (int i = 0; i < 4; i++)
        tile[threadIdx.y + i * 8][threadIdx.x] =
            xb[(size_t)(c0 + threadIdx.y + i * 8) * HWSZ + p0 + threadIdx.x];
    __syncthreads();
#pragma unroll
    for (int i = 0; i < 4; i++)
        xt[((size_t)b * HWSZ + p0 + threadIdx.y + i * 8) * CDIM + c0 + threadIdx.x] =
            tile[threadIdx.x][threadIdx.y + i * 8];
}
__global__ void transpose_out_kernel(const float* __restrict__ xt, float* __restrict__ out) {
    __shared__ float tile[32][33];
    const int b = blockIdx.z, p0 = blockIdx.x * 32, c0 = blockIdx.y * 32;
#pragma unroll
    for (int i = 0; i < 4; i++)
        tile[threadIdx.y + i * 8][threadIdx.x] =
            xt[((size_t)b * HWSZ + p0 + threadIdx.y + i * 8) * CDIM + c0 + threadIdx.x];
    __syncthreads();
    float* ob = out + (size_t)b * CDIM * HWSZ;
#pragma unroll
    for (int i = 0; i < 4; i++)
        ob[(size_t)(c0 + threadIdx.y + i * 8) * HWSZ + p0 + threadIdx.x] =
            tile[threadIdx.x][threadIdx.y + i * 8];
}

// ---------------- LayerNorm (fp32 in, fp8 out) ----------------
__global__ void ln_kernel(const float* __restrict__ in, fp8* __restrict__ out,
                          const float* __restrict__ g, const float* __restrict__ b) {
    const int row = blockIdx.x * 8 + threadIdx.y;
    const int lane = threadIdx.x;
    const float* xr = in + (size_t)row * CDIM;
    float v[12];
    float s = 0.f;
#pragma unroll
    for (int i = 0; i < 12; i++) { v[i] = xr[lane + i * 32]; s += v[i]; }
#pragma unroll
    for (int o = 16; o > 0; o >>= 1) s += __shfl_xor_sync(0xffffffffu, s, o);
    const float mean = s * (1.f / CDIM);
    float q = 0.f;
#pragma unroll
    for (int i = 0; i < 12; i++) { float d = v[i] - mean; q += d * d; }
#pragma unroll
    for (int o = 16; o > 0; o >>= 1) q += __shfl_xor_sync(0xffffffffu, q, o);
    const float r = rsqrtf(q * (1.f / CDIM) + 1e-5f);
    fp8* orow = out + (size_t)row * CDIM;
#pragma unroll
    for (int i = 0; i < 12; i++) {
        int c = lane + i * 32;
        orow[c] = fp8((v[i] - mean) * r * g[c] + b[c]);
    }
}

// ---------------- attention: bf16 KV in smem, fp8 out ----------------
__global__ __launch_bounds__(64) void attn_kernel(const bf16* __restrict__ qkv,
                                                  fp8* __restrict__ o) {
    __shared__ __nv_bfloat162 sk[64][24];
    __shared__ __nv_bfloat162 sv[64][24];
    __shared__ float ss[64][65];
    __shared__ int   srow[64];

    const int wnd  = blockIdx.x;
    const int head = blockIdx.y;
    const int b  = wnd / (GSZ * GSZ);
    const int gy = (wnd / GSZ) % GSZ;
    const int gx = wnd % GSZ;
    const int tid = threadIdx.x;
    {
        int sy = tid / SPR, sx = tid % SPR;
        srow[tid] = b * HWSZ + (sy * GSZ + gy) * HDIM + (sx * GSZ + gx);
    }
    __syncthreads();
    for (int i = tid; i < 64 * 24; i += 64) {
        int t = i / 24, d2 = i % 24;
        size_t base = (size_t)srow[t] * (3 * CDIM) + head * HD + d2 * 2;
        sk[t][d2] = *(const __nv_bfloat162*)&qkv[base + CDIM];
        sv[t][d2] = *(const __nv_bfloat162*)&qkv[base + 2 * CDIM];
    }
    __syncthreads();
    const float scale = 0.14433756729740643f;
    const bf16* qp = qkv + (size_t)srow[tid] * (3 * CDIM) + head * HD;
    float q[HD];
#pragma unroll
    for (int d = 0; d < HD; d++) q[d] = __bfloat162float(qp[d]) * scale;

    for (int j = 0; j < 64; j++) {
        float a = 0.f;
#pragma unroll
        for (int d2 = 0; d2 < 24; d2++) {
            float2 kv = __bfloat1622float2(sk[j][d2]);
            a = fmaf(q[2 * d2], kv.x, a);
            a = fmaf(q[2 * d2 + 1], kv.y, a);
        }
        ss[tid][j] = a;
    }
    float mx = -1e30f;
    for (int j = 0; j < 64; j++) mx = fmaxf(mx, ss[tid][j]);
    float sum = 0.f;
    for (int j = 0; j < 64; j++) {
        float p = expf(ss[tid][j] - mx);
        ss[tid][j] = p; sum += p;
    }
    const float inv = 1.f / sum;
    float oacc[HD];
#pragma unroll
    for (int d = 0; d < HD; d++) oacc[d] = 0.f;
    for (int j = 0; j < 64; j++) {
        float p = ss[tid][j];
#pragma unroll
        for (int d2 = 0; d2 < 24; d2++) {
            float2 vv = __bfloat1622float2(sv[j][d2]);
            oacc[2 * d2]     = fmaf(p, vv.x, oacc[2 * d2]);
            oacc[2 * d2 + 1] = fmaf(p, vv.y, oacc[2 * d2 + 1]);
        }
    }
    fp8* op = o + (size_t)srow[tid] * CDIM + head * HD;
#pragma unroll
    for (int d = 0; d < HD; d++) op[d] = fp8(oacc[d] * inv);
}

// ---------------- depthwise 3x3 + bias + exact GELU (bf16 in, fp8 out) ----------------
__global__ void dwconv_gelu_kernel(const bf16* __restrict__ m, const float* __restrict__ w,
                                   const float* __restrict__ bias, fp8* __restrict__ out) {
    const int bn = blockIdx.x;
    const int c  = (blockIdx.y * 256 + threadIdx.x) * 2;
    const int b  = bn / HWSZ;
    const int p  = bn % HWSZ;
    const int y  = p / HDIM;
    const int x  = p % HDIM;

    float w0[9], w1[9];
#pragma unroll
    for (int i = 0; i < 9; i++) { w0[i] = w[c * 9 + i]; w1[i] = w[(c + 1) * 9 + i]; }

    float a0 = bias[c], a1 = bias[c + 1];
#pragma unroll
    for (int ky = 0; ky < 3; ky++) {
        int yy = y + ky - 1;
        if (yy < 0 || yy >= HDIM) continue;
#pragma unroll
        for (int kx = 0; kx < 3; kx++) {
            int xx = x + kx - 1;
            if (xx < 0 || xx >= HDIM) continue;
            __nv_bfloat162 v = *(const __nv_bfloat162*)
                &m[((size_t)b * HWSZ + yy * HDIM + xx) * HID + c];
            a0 = fmaf(__bfloat162float(v.x), w0[ky * 3 + kx], a0);
            a1 = fmaf(__bfloat162float(v.y), w1[ky * 3 + kx], a1);
        }
    }
    const float k = 0.70710678118654752f;
    float gl0 = 0.5f * a0 * (1.f + erff(a0 * k));
    float gl1 = 0.5f * a1 * (1.f + erff(a1 * k));
    out[(size_t)bn * HID + c]     = fp8(gl0);
    out[(size_t)bn * HID + c + 1] = fp8(gl1);
}

// ---------------- launch ----------------
extern "C" void kernel_launch(void* const* d_in, const int* in_sizes, int n_in,
                              void* d_out, int out_size) {
    const float* x      = (const float*)d_in[0];
    const float* ln1_g  = (const float*)d_in[1];
    const float* ln1_b  = (const float*)d_in[2];
    const float* qkv_w  = (const float*)d_in[3];
    const float* proj_w = (const float*)d_in[4];
    const float* proj_b = (const float*)d_in[5];
    const float* ln2_g  = (const float*)d_in[6];
    const float* ln2_b  = (const float*)d_in[7];
    const float* fc1_w  = (const float*)d_in[8];
    const float* fc1_b  = (const float*)d_in[9];
    const float* dw_w   = (const float*)d_in[10];
    const float* dw_b   = (const float*)d_in[11];
    const float* fc2_w  = (const float*)d_in[12];
    const float* fc2_b  = (const float*)d_in[13];
    const float* gamma1 = (const float*)d_in[14];
    const float* gamma2 = (const float*)d_in[15];
    float* out = (float*)d_out;

    float *xt; bf16 *qkvb, *mb; fp8 *h8, *mg8, *wq, *wp, *w1, *w2;
    cudaGetSymbolAddress((void**)&xt,   g_xt);
    cudaGetSymbolAddress((void**)&h8,   g_h8);
    cudaGetSymbolAddress((void**)&qkvb, g_qkvb);
    cudaGetSymbolAddress((void**)&mb,   g_mb);
    cudaGetSymbolAddress((void**)&mg8,  g_mg8);
    cudaGetSymbolAddress((void**)&wq,   g_wqkv8);
    cudaGetSymbolAddress((void**)&wp,   g_wproj8);
    cudaGetSymbolAddress((void**)&w1,   g_wfc18);
    cudaGetSymbolAddress((void**)&w2,   g_wfc28);

    static bool attr_done = false;
    if (!attr_done) {
        cudaFuncSetAttribute(gemm_fp8_kernel<0>,
                             cudaFuncAttributeMaxDynamicSharedMemorySize, GEMM_SMEM);
        cudaFuncSetAttribute(gemm_fp8_kernel<1>,
                             cudaFuncAttributeMaxDynamicSharedMemorySize, GEMM_SMEM);
        attr_done = true;
    }

    dim3 tb32x8(32, 8);

    wconv_kernel<<<dim3(1152 / 32, CDIM / 32), tb32x8>>>(qkv_w,  wq, CDIM, 1152);
    wconv_kernel<<<dim3(CDIM / 32, CDIM / 32), tb32x8>>>(proj_w, wp, CDIM, CDIM);
    wconv_kernel<<<dim3(HID  / 32, CDIM / 32), tb32x8>>>(fc1_w,  w1, CDIM, HID);
    wconv_kernel<<<dim3(CDIM / 32, HID  / 32), tb32x8>>>(fc2_w,  w2, HID,  CDIM);

    transpose_in_kernel<<<dim3(HWSZ / 32, CDIM / 32, BATCH), tb32x8>>>(x, xt);
    ln_kernel<<<NTOK / 8, tb32x8>>>(xt, h8, ln1_g, ln1_b);

    gemm_fp8_kernel<0><<<dim3(1152 / 128, NTOK / 128), 128, GEMM_SMEM>>>(
        h8, wq, nullptr, nullptr, nullptr, qkvb, NTOK, 1152, CDIM);
    attn_kernel<<<dim3(BATCH * GSZ * GSZ, HEADS), 64>>>(qkvb, h8);
    gemm_fp8_kernel<1><<<dim3(CDIM / 128, NTOK / 128), 128, GEMM_SMEM>>>(
        h8, wp, proj_b, xt, gamma1, xt, NTOK, CDIM, CDIM);
    ln_kernel<<<NTOK / 8, tb32x8>>>(xt, h8, ln2_g, ln2_b);
    gemm_fp8_kernel<0><<<dim3(HID / 128, NTOK / 128), 128, GEMM_SMEM>>>(
        h8, w1, fc1_b, nullptr, nullptr, mb, NTOK, HID, CDIM);
    dwconv_gelu_kernel<<<dim3(NTOK, HID / 512), 256>>>(mb, dw_w, dw_b, mg8);
    gemm_fp8_kernel<1><<<dim3(CDIM / 128, NTOK / 128), 128, GEMM_SMEM>>>(
        mg8, w2, fc2_b, xt, gamma2, xt, NTOK, CDIM, HID);

    transpose_out_kernel<<<dim3(HWSZ / 32, CDIM / 32, BATCH), tb32x8>>>(xt, out);
}

// round 7
// speedup vs baseline: 3.5481x; 1.1009x over previous
#include <cuda_runtime.h>
#include <cuda_bf16.h>
#include <cuda_fp8.h>
#include <cstdint>
#include <math.h>

#define BATCH 32
#define CDIM  384
#define HDIM  56
#define HWSZ  3136
#define NTOK  100352
#define HID   1536
#define HEADS 8
#define HD    48
#define GSZ   7
#define SPR   8

typedef __nv_bfloat16 bf16;
typedef __nv_fp8_e4m3 fp8;

#define WSCALE     64.0f
#define INV_WSCALE 0.015625f

// ---------------- scratch ----------------
__device__ float g_xt  [(size_t)NTOK * CDIM];
__device__ fp8   g_h8  [(size_t)NTOK * CDIM];
__device__ bf16  g_qkvb[(size_t)NTOK * 3 * CDIM];
__device__ bf16  g_mb  [(size_t)NTOK * HID];
__device__ fp8   g_mg8 [(size_t)NTOK * HID];
__device__ fp8   g_wqkv8 [3 * CDIM * CDIM];
__device__ fp8   g_wproj8[CDIM * CDIM];
__device__ fp8   g_wfc18 [HID * CDIM];
__device__ fp8   g_wfc28 [CDIM * HID];

__device__ __forceinline__ unsigned int saddr(const void* p) {
    return (unsigned int)__cvta_generic_to_shared(p);
}
__device__ __forceinline__ void cp16(unsigned int dst, const void* src) {
    asm volatile("cp.async.cg.shared.global [%0], [%1], 16;" :: "r"(dst), "l"(src));
}

// ================== FP8 e4m3 tensor-core GEMM, BK=128 ==================
// C[M,N] = (A @ Bw^T) * INV_WSCALE.  A=[M][K] fp8, Bw=[N][K] fp8 (x64).
// Block 128x128, 4 warps (64x64 each), BK=128 bytes, 2-stage ring.
#define PADB 144           // bytes per smem row (128B data + 16B pad)
#define STG 2
#define TILEB (128 * PADB) // 18432 B

template<int EPI>
__global__ __launch_bounds__(128) void gemm_fp8_kernel(
    const fp8* __restrict__ A, const fp8* __restrict__ Bw,
    const float* __restrict__ bias, const float* __restrict__ res,
    const float* __restrict__ gamma, void* __restrict__ Cout,
    int M, int N, int K)
{
    extern __shared__ char sm8[];
    char* As = sm8;
    char* Bs = sm8 + STG * TILEB;

    const int tid  = threadIdx.x;
    const int lane = tid & 31;
    const int warp = tid >> 5;
    const int wm   = (warp >> 1) * 64;
    const int wn   = (warp & 1) * 64;
    const int bm   = blockIdx.y * 128;
    const int bn   = blockIdx.x * 128;

    float acc[4][8][4];
#pragma unroll
    for (int i = 0; i < 4; i++)
#pragma unroll
        for (int j = 0; j < 8; j++)
#pragma unroll
            for (int r = 0; r < 4; r++) acc[i][j][r] = 0.f;

    const int a_row  = lane & 15;
    const int a_kb   = (lane >> 4) * 16;
    const int b_nrow = ((lane >> 4) * 8) + (lane & 7);
    const int b_kb   = ((lane >> 3) & 1) * 16;

    const int iters = K / 128;

    // loader: 8 chunks of 16B per 128B row; 1024 chunks / 128 threads = 8 each per matrix
    auto load_stage = [&](int s, int k0) {
        char* as = As + s * TILEB;
        char* bs = Bs + s * TILEB;
#pragma unroll
        for (int u = 0; u < 8; u++) {
            int id = u * 128 + tid;
            int row = id >> 3, c = id & 7;
            cp16(saddr(as + row * PADB + c * 16),
                 (const char*)A + (size_t)(bm + row) * K + k0 + c * 16);
        }
#pragma unroll
        for (int u = 0; u < 8; u++) {
            int id = u * 128 + tid;
            int row = id >> 3, c = id & 7;
            cp16(saddr(bs + row * PADB + c * 16),
                 (const char*)Bw + (size_t)(bn + row) * K + k0 + c * 16);
        }
        asm volatile("cp.async.commit_group;");
    };

    load_stage(0, 0);
    if (iters > 1) load_stage(1, 128);

    for (int it = 0; it < iters; it++) {
        if (it + 1 < iters)
            asm volatile("cp.async.wait_group 1;" ::: "memory");
        else
            asm volatile("cp.async.wait_group 0;" ::: "memory");
        __syncthreads();

        const char* as = As + (it & 1) * TILEB;
        const char* bs = Bs + (it & 1) * TILEB;

#pragma unroll
        for (int ks = 0; ks < 4; ks++) {       // four k32 steps per BK=128
            unsigned int a[4][4];
#pragma unroll
            for (int i = 0; i < 4; i++) {
                unsigned int ad = saddr(as + (wm + i * 16 + a_row) * PADB + ks * 32 + a_kb);
                asm volatile("ldmatrix.sync.aligned.m8n8.x4.shared.b16 {%0,%1,%2,%3}, [%4];"
                             : "=r"(a[i][0]), "=r"(a[i][1]), "=r"(a[i][2]), "=r"(a[i][3])
                             : "r"(ad));
            }
            unsigned int b[8][2];
#pragma unroll
            for (int j2 = 0; j2 < 4; j2++) {
                unsigned int bd = saddr(bs + (wn + j2 * 16 + b_nrow) * PADB + ks * 32 + b_kb);
                unsigned int r0, r1, r2, r3;
                asm volatile("ldmatrix.sync.aligned.m8n8.x4.shared.b16 {%0,%1,%2,%3}, [%4];"
                             : "=r"(r0), "=r"(r1), "=r"(r2), "=r"(r3) : "r"(bd));
                b[j2 * 2 + 0][0] = r0; b[j2 * 2 + 0][1] = r1;
                b[j2 * 2 + 1][0] = r2; b[j2 * 2 + 1][1] = r3;
            }
#pragma unroll
            for (int i = 0; i < 4; i++)
#pragma unroll
                for (int j = 0; j < 8; j++)
                    asm volatile(
                        "mma.sync.aligned.m16n8k32.row.col.f32.e4m3.e4m3.f32 "
                        "{%0,%1,%2,%3}, {%4,%5,%6,%7}, {%8,%9}, {%0,%1,%2,%3};"
                        : "+f"(acc[i][j][0]), "+f"(acc[i][j][1]),
                          "+f"(acc[i][j][2]), "+f"(acc[i][j][3])
                        : "r"(a[i][0]), "r"(a[i][1]), "r"(a[i][2]), "r"(a[i][3]),
                          "r"(b[j][0]), "r"(b[j][1]));
        }
        __syncthreads();
        if (it + 2 < iters) load_stage(it & 1, (it + 2) * 128);
    }

    // -------- epilogue --------
    const int rbase = bm + wm + (lane >> 2);
    const int cbase = bn + wn + (lane & 3) * 2;
#pragma unroll
    for (int j = 0; j < 8; j++) {
        const int c = cbase + j * 8;
        const float b0 = bias ? bias[c] : 0.f;
        const float b1 = bias ? bias[c + 1] : 0.f;
        float g0 = 1.f, g1 = 1.f;
        if (EPI == 1) { g0 = gamma[c]; g1 = gamma[c + 1]; }
#pragma unroll
        for (int i = 0; i < 4; i++) {
#pragma unroll
            for (int h = 0; h < 2; h++) {
                const int r = rbase + i * 16 + h * 8;
                const float v0 = acc[i][j][h * 2 + 0] * INV_WSCALE + b0;
                const float v1 = acc[i][j][h * 2 + 1] * INV_WSCALE + b1;
                if (EPI == 0) {
                    bf16* C = (bf16*)Cout;
                    __nv_bfloat162 pv;
                    pv.x = __float2bfloat16(v0);
                    pv.y = __float2bfloat16(v1);
                    *(__nv_bfloat162*)&C[(size_t)r * N + c] = pv;
                } else {
                    float* C = (float*)Cout;
                    float2 rr = *(const float2*)&res[(size_t)r * N + c];
                    float2 o;
                    o.x = rr.x + g0 * v0;
                    o.y = rr.y + g1 * v1;
                    *(float2*)&C[(size_t)r * N + c] = o;
                }
            }
        }
    }
}
#define GEMM_SMEM (STG * 2 * TILEB)

// ---------------- merged weight transpose+convert (1 launch, z selects matrix) ----------------
__global__ void wconv_all_kernel(const float* __restrict__ qkv_w, const float* __restrict__ proj_w,
                                 const float* __restrict__ fc1_w, const float* __restrict__ fc2_w,
                                 fp8* __restrict__ wq, fp8* __restrict__ wp,
                                 fp8* __restrict__ w1, fp8* __restrict__ w2) {
    const float* w; fp8* o; int K, N;
    switch (blockIdx.z) {
        case 0: w = qkv_w;  o = wq; K = CDIM; N = 3 * CDIM; break;
        case 1: w = proj_w; o = wp; K = CDIM; N = CDIM;     break;
        case 2: w = fc1_w;  o = w1; K = CDIM; N = HID;      break;
        default:w = fc2_w;  o = w2; K = HID;  N = CDIM;     break;
    }
    const int n0 = blockIdx.x * 32, k0 = blockIdx.y * 32;
    if (n0 >= N || k0 >= K) return;
    __shared__ float tile[32][33];
#pragma unroll
    for (int i = 0; i < 4; i++)
        tile[threadIdx.y + i * 8][threadIdx.x] =
            w[(size_t)(k0 + threadIdx.y + i * 8) * N + n0 + threadIdx.x];
    __syncthreads();
#pragma unroll
    for (int i = 0; i < 4; i++)
        o[(size_t)(n0 + threadIdx.y + i * 8) * K + k0 + threadIdx.x] =
            fp8(tile[threadIdx.x][threadIdx.y + i * 8] * WSCALE);
}

// ---------------- transposes ----------------
__global__ void transpose_in_kernel(const float* __restrict__ x, float* __restrict__ xt) {
    __shared__ float tile[32][33];
    const int b = blockIdx.z, p0 = blockIdx.x * 32, c0 = blockIdx.y * 32;
    const float* xb = x + (size_t)b * CDIM * HWSZ;
#pragma unroll
    for (int i = 0; i < 4; i++)
        tile[threadIdx.y + i * 8][threadIdx.x] =
            xb[(size_t)(c0 + threadIdx.y + i * 8) * HWSZ + p0 + threadIdx.x];
    __syncthreads();
#pragma unroll
    for (int i = 0; i < 4; i++)
        xt[((size_t)b * HWSZ + p0 + threadIdx.y + i * 8) * CDIM + c0 + threadIdx.x] =
            tile[threadIdx.x][threadIdx.y + i * 8];
}
__global__ void transpose_out_kernel(const float* __restrict__ xt, float* __restrict__ out) {
    __shared__ float tile[32][33];
    const int b = blockIdx.z, p0 = blockIdx.x * 32, c0 = blockIdx.y * 32;
#pragma unroll
    for (int i = 0; i < 4; i++)
        tile[threadIdx.y + i * 8][threadIdx.x] =
            xt[((size_t)b * HWSZ + p0 + threadIdx.y + i * 8) * CDIM + c0 + threadIdx.x];
    __syncthreads();
    float* ob = out + (size_t)b * CDIM * HWSZ;
#pragma unroll
    for (int i = 0; i < 4; i++)
        ob[(size_t)(c0 + threadIdx.y + i * 8) * HWSZ + p0 + threadIdx.x] =
            tile[threadIdx.x][threadIdx.y + i * 8];
}

// ---------------- LayerNorm (fp32 in, fp8 out) ----------------
__global__ void ln_kernel(const float* __restrict__ in, fp8* __restrict__ out,
                          const float* __restrict__ g, const float* __restrict__ b) {
    const int row = blockIdx.x * 8 + threadIdx.y;
    const int lane = threadIdx.x;
    const float* xr = in + (size_t)row * CDIM;
    float v[12];
    float s = 0.f;
#pragma unroll
    for (int i = 0; i < 12; i++) { v[i] = xr[lane + i * 32]; s += v[i]; }
#pragma unroll
    for (int o = 16; o > 0; o >>= 1) s += __shfl_xor_sync(0xffffffffu, s, o);
    const float mean = s * (1.f / CDIM);
    float q = 0.f;
#pragma unroll
    for (int i = 0; i < 12; i++) { float d = v[i] - mean; q += d * d; }
#pragma unroll
    for (int o = 16; o > 0; o >>= 1) q += __shfl_xor_sync(0xffffffffu, q, o);
    const float r = rsqrtf(q * (1.f / CDIM) + 1e-5f);
    fp8* orow = out + (size_t)row * CDIM;
#pragma unroll
    for (int i = 0; i < 12; i++) {
        int c = lane + i * 32;
        orow[c] = fp8((v[i] - mean) * r * g[c] + b[c]);
    }
}

// ---------------- attention: packed bf16x2 HFMA2 ----------------
__global__ __launch_bounds__(64) void attn_kernel(const bf16* __restrict__ qkv,
                                                  fp8* __restrict__ o) {
    __shared__ __nv_bfloat162 sk[64][24];
    __shared__ __nv_bfloat162 sv[64][24];
    __shared__ float ss[64][65];
    __shared__ int   srow[64];

    const int wnd  = blockIdx.x;
    const int head = blockIdx.y;
    const int b  = wnd / (GSZ * GSZ);
    const int gy = (wnd / GSZ) % GSZ;
    const int gx = wnd % GSZ;
    const int tid = threadIdx.x;
    {
        int sy = tid / SPR, sx = tid % SPR;
        srow[tid] = b * HWSZ + (sy * GSZ + gy) * HDIM + (sx * GSZ + gx);
    }
    __syncthreads();
    for (int i = tid; i < 64 * 24; i += 64) {
        int t = i / 24, d2 = i % 24;
        size_t base = (size_t)srow[t] * (3 * CDIM) + head * HD + d2 * 2;
        sk[t][d2] = *(const __nv_bfloat162*)&qkv[base + CDIM];
        sv[t][d2] = *(const __nv_bfloat162*)&qkv[base + 2 * CDIM];
    }
    __syncthreads();
    const float scale = 0.14433756729740643f;
    const bf16* qp = qkv + (size_t)srow[tid] * (3 * CDIM) + head * HD;
    __nv_bfloat162 q2[24];
#pragma unroll
    for (int d2 = 0; d2 < 24; d2++) {
        float f0 = __bfloat162float(qp[2 * d2]) * scale;
        float f1 = __bfloat162float(qp[2 * d2 + 1]) * scale;
        q2[d2] = __floats2bfloat162_rn(f0, f1);
    }
    for (int j = 0; j < 64; j++) {
        __nv_bfloat162 a2 = __floats2bfloat162_rn(0.f, 0.f);
#pragma unroll
        for (int d2 = 0; d2 < 24; d2++) a2 = __hfma2(q2[d2], sk[j][d2], a2);
        ss[tid][j] = __low2float(a2) + __high2float(a2);
    }
    float mx = -1e30f;
    for (int j = 0; j < 64; j++) mx = fmaxf(mx, ss[tid][j]);
    float sum = 0.f;
    for (int j = 0; j < 64; j++) {
        float p = expf(ss[tid][j] - mx);
        ss[tid][j] = p; sum += p;
    }
    const float inv = 1.f / sum;
    __nv_bfloat162 oacc[24];
#pragma unroll
    for (int d2 = 0; d2 < 24; d2++) oacc[d2] = __floats2bfloat162_rn(0.f, 0.f);
    for (int j = 0; j < 64; j++) {
        __nv_bfloat162 p2 = __float2bfloat162_rn(ss[tid][j]);
#pragma unroll
        for (int d2 = 0; d2 < 24; d2++) oacc[d2] = __hfma2(p2, sv[j][d2], oacc[d2]);
    }
    fp8* op = o + (size_t)srow[tid] * CDIM + head * HD;
#pragma unroll
    for (int d2 = 0; d2 < 24; d2++) {
        op[2 * d2]     = fp8(__low2float(oacc[d2]) * inv);
        op[2 * d2 + 1] = fp8(__high2float(oacc[d2]) * inv);
    }
}

// ---------------- depthwise 3x3 + bias + exact GELU (packed HFMA2) ----------------
__global__ void dwconv_gelu_kernel(const bf16* __restrict__ m, const float* __restrict__ w,
                                   const float* __restrict__ bias, fp8* __restrict__ out) {
    const int bn = blockIdx.x;
    const int c  = (blockIdx.y * 256 + threadIdx.x) * 2;
    const int b  = bn / HWSZ;
    const int p  = bn % HWSZ;
    const int y  = p / HDIM;
    const int x  = p % HDIM;

    __nv_bfloat162 wp[9];
#pragma unroll
    for (int i = 0; i < 9; i++)
        wp[i] = __floats2bfloat162_rn(w[c * 9 + i], w[(c + 1) * 9 + i]);

    __nv_bfloat162 acc2 = __floats2bfloat162_rn(0.f, 0.f);
#pragma unroll
    for (int ky = 0; ky < 3; ky++) {
        int yy = y + ky - 1;
        if (yy < 0 || yy >= HDIM) continue;
#pragma unroll
        for (int kx = 0; kx < 3; kx++) {
            int xx = x + kx - 1;
            if (xx < 0 || xx >= HDIM) continue;
            __nv_bfloat162 v = *(const __nv_bfloat162*)
                &m[((size_t)b * HWSZ + yy * HDIM + xx) * HID + c];
            acc2 = __hfma2(v, wp[ky * 3 + kx], acc2);
        }
    }
    float a0 = __low2float(acc2) + bias[c];
    float a1 = __high2float(acc2) + bias[c + 1];
    const float k = 0.70710678118654752f;
    out[(size_t)bn * HID + c]     = fp8(0.5f * a0 * (1.f + erff(a0 * k)));
    out[(size_t)bn * HID + c + 1] = fp8(0.5f * a1 * (1.f + erff(a1 * k)));
}

// ---------------- launch ----------------
extern "C" void kernel_launch(void* const* d_in, const int* in_sizes, int n_in,
                              void* d_out, int out_size) {
    const float* x      = (const float*)d_in[0];
    const float* ln1_g  = (const float*)d_in[1];
    const float* ln1_b  = (const float*)d_in[2];
    const float* qkv_w  = (const float*)d_in[3];
    const float* proj_w = (const float*)d_in[4];
    const float* proj_b = (const float*)d_in[5];
    const float* ln2_g  = (const float*)d_in[6];
    const float* ln2_b  = (const float*)d_in[7];
    const float* fc1_w  = (const float*)d_in[8];
    const float* fc1_b  = (const float*)d_in[9];
    const float* dw_w   = (const float*)d_in[10];
    const float* dw_b   = (const float*)d_in[11];
    const float* fc2_w  = (const float*)d_in[12];
    const float* fc2_b  = (const float*)d_in[13];
    const float* gamma1 = (const float*)d_in[14];
    const float* gamma2 = (const float*)d_in[15];
    float* out = (float*)d_out;

    float *xt; bf16 *qkvb, *mb; fp8 *h8, *mg8, *wq, *wp, *w1, *w2;
    cudaGetSymbolAddress((void**)&xt,   g_xt);
    cudaGetSymbolAddress((void**)&h8,   g_h8);
    cudaGetSymbolAddress((void**)&qkvb, g_qkvb);
    cudaGetSymbolAddress((void**)&mb,   g_mb);
    cudaGetSymbolAddress((void**)&mg8,  g_mg8);
    cudaGetSymbolAddress((void**)&wq,   g_wqkv8);
    cudaGetSymbolAddress((void**)&wp,   g_wproj8);
    cudaGetSymbolAddress((void**)&w1,   g_wfc18);
    cudaGetSymbolAddress((void**)&w2,   g_wfc28);

    static bool attr_done = false;
    if (!attr_done) {
        cudaFuncSetAttribute(gemm_fp8_kernel<0>,
                             cudaFuncAttributeMaxDynamicSharedMemorySize, GEMM_SMEM);
        cudaFuncSetAttribute(gemm_fp8_kernel<1>,
                             cudaFuncAttributeMaxDynamicSharedMemorySize, GEMM_SMEM);
        attr_done = true;
    }

    dim3 tb32x8(32, 8);

    wconv_all_kernel<<<dim3(48, 48, 4), tb32x8>>>(qkv_w, proj_w, fc1_w, fc2_w,
                                                  wq, wp, w1, w2);
    transpose_in_kernel<<<dim3(HWSZ / 32, CDIM / 32, BATCH), tb32x8>>>(x, xt);
    ln_kernel<<<NTOK / 8, tb32x8>>>(xt, h8, ln1_g, ln1_b);

    gemm_fp8_kernel<0><<<dim3(1152 / 128, NTOK / 128), 128, GEMM_SMEM>>>(
        h8, wq, nullptr, nullptr, nullptr, qkvb, NTOK, 1152, CDIM);
    attn_kernel<<<dim3(BATCH * GSZ * GSZ, HEADS), 64>>>(qkvb, h8);
    gemm_fp8_kernel<1><<<dim3(CDIM / 128, NTOK / 128), 128, GEMM_SMEM>>>(
        h8, wp, proj_b, xt, gamma1, xt, NTOK, CDIM, CDIM);
    ln_kernel<<<NTOK / 8, tb32x8>>>(xt, h8, ln2_g, ln2_b);
    gemm_fp8_kernel<0><<<dim3(HID / 128, NTOK / 128), 128, GEMM_SMEM>>>(
        h8, w1, fc1_b, nullptr, nullptr, mb, NTOK, HID, CDIM);
    dwconv_gelu_kernel<<<dim3(NTOK, HID / 512), 256>>>(mb, dw_w, dw_b, mg8);
    gemm_fp8_kernel<1><<<dim3(CDIM / 128, NTOK / 128), 128, GEMM_SMEM>>>(
        mg8, w2, fc2_b, xt, gamma2, xt, NTOK, CDIM, HID);

    transpose_out_kernel<<<dim3(HWSZ / 32, CDIM / 32, BATCH), tb32x8>>>(xt, out);
}

// round 8
// speedup vs baseline: 3.7678x; 1.0619x over previous
#include <cuda_runtime.h>
#include <cuda_bf16.h>
#include <cuda_fp8.h>
#include <cstdint>
#include <math.h>

#define BATCH 32
#define CDIM  384
#define HDIM  56
#define HWSZ  3136
#define NTOK  100352
#define HID   1536
#define HEADS 8
#define HD    48
#define GSZ   7
#define SPR   8

typedef __nv_bfloat16 bf16;
typedef __nv_fp8_e4m3 fp8;

#define WSCALE     64.0f
#define INV_WSCALE 0.015625f

// ---------------- scratch ----------------
__device__ float g_xt  [(size_t)NTOK * CDIM];
__device__ fp8   g_h8  [(size_t)NTOK * CDIM];
__device__ bf16  g_qkvb[(size_t)NTOK * 3 * CDIM];
__device__ bf16  g_mb  [(size_t)NTOK * HID];
__device__ fp8   g_mg8 [(size_t)NTOK * HID];
__device__ fp8   g_wqkv8 [3 * CDIM * CDIM];
__device__ fp8   g_wproj8[CDIM * CDIM];
__device__ fp8   g_wfc18 [HID * CDIM];
__device__ fp8   g_wfc28 [CDIM * HID];

__device__ __forceinline__ unsigned int saddr(const void* p) {
    return (unsigned int)__cvta_generic_to_shared(p);
}
__device__ __forceinline__ void cp16(unsigned int dst, const void* src) {
    asm volatile("cp.async.cg.shared.global [%0], [%1], 16;" :: "r"(dst), "l"(src));
}

// ================== FP8 e4m3 tensor-core GEMM ==================
// Block 128x128, 8 warps (warp tile 64x32), BK=128 bytes, 2-stage ring.
#define PADB 144
#define STG 2
#define TILEB (128 * PADB)

template<int EPI>
__global__ __launch_bounds__(256) void gemm_fp8_kernel(
    const fp8* __restrict__ A, const fp8* __restrict__ Bw,
    const float* __restrict__ bias, const float* __restrict__ res,
    const float* __restrict__ gamma, void* __restrict__ Cout,
    int M, int N, int K)
{
    extern __shared__ char sm8[];
    char* As = sm8;
    char* Bs = sm8 + STG * TILEB;

    const int tid  = threadIdx.x;
    const int lane = tid & 31;
    const int warp = tid >> 5;
    const int wm   = (warp >> 2) * 64;   // 2 warp rows
    const int wn   = (warp & 3) * 32;    // 4 warp cols
    const int bm   = blockIdx.y * 128;
    const int bn   = blockIdx.x * 128;

    float acc[4][4][4];
#pragma unroll
    for (int i = 0; i < 4; i++)
#pragma unroll
        for (int j = 0; j < 4; j++)
#pragma unroll
            for (int r = 0; r < 4; r++) acc[i][j][r] = 0.f;

    const int a_row  = lane & 15;
    const int a_kb   = (lane >> 4) * 16;
    const int b_nrow = ((lane >> 4) * 8) + (lane & 7);
    const int b_kb   = ((lane >> 3) & 1) * 16;

    const int iters = K / 128;

    // loader: 8 chunks of 16B per 128B row; 1024 chunks / 256 threads = 4 per matrix
    auto load_stage = [&](int s, int k0) {
        char* as = As + s * TILEB;
        char* bs = Bs + s * TILEB;
#pragma unroll
        for (int u = 0; u < 4; u++) {
            int id = u * 256 + tid;
            int row = id >> 3, c = id & 7;
            cp16(saddr(as + row * PADB + c * 16),
                 (const char*)A + (size_t)(bm + row) * K + k0 + c * 16);
        }
#pragma unroll
        for (int u = 0; u < 4; u++) {
            int id = u * 256 + tid;
            int row = id >> 3, c = id & 7;
            cp16(saddr(bs + row * PADB + c * 16),
                 (const char*)Bw + (size_t)(bn + row) * K + k0 + c * 16);
        }
        asm volatile("cp.async.commit_group;");
    };

    load_stage(0, 0);
    if (iters > 1) load_stage(1, 128);

    for (int it = 0; it < iters; it++) {
        if (it + 1 < iters)
            asm volatile("cp.async.wait_group 1;" ::: "memory");
        else
            asm volatile("cp.async.wait_group 0;" ::: "memory");
        __syncthreads();

        const char* as = As + (it & 1) * TILEB;
        const char* bs = Bs + (it & 1) * TILEB;

#pragma unroll
        for (int ks = 0; ks < 4; ks++) {
            unsigned int a[4][4];
#pragma unroll
            for (int i = 0; i < 4; i++) {
                unsigned int ad = saddr(as + (wm + i * 16 + a_row) * PADB + ks * 32 + a_kb);
                asm volatile("ldmatrix.sync.aligned.m8n8.x4.shared.b16 {%0,%1,%2,%3}, [%4];"
                             : "=r"(a[i][0]), "=r"(a[i][1]), "=r"(a[i][2]), "=r"(a[i][3])
                             : "r"(ad));
            }
            unsigned int b[4][2];
#pragma unroll
            for (int j2 = 0; j2 < 2; j2++) {
                unsigned int bd = saddr(bs + (wn + j2 * 16 + b_nrow) * PADB + ks * 32 + b_kb);
                unsigned int r0, r1, r2, r3;
                asm volatile("ldmatrix.sync.aligned.m8n8.x4.shared.b16 {%0,%1,%2,%3}, [%4];"
                             : "=r"(r0), "=r"(r1), "=r"(r2), "=r"(r3) : "r"(bd));
                b[j2 * 2 + 0][0] = r0; b[j2 * 2 + 0][1] = r1;
                b[j2 * 2 + 1][0] = r2; b[j2 * 2 + 1][1] = r3;
            }
#pragma unroll
            for (int i = 0; i < 4; i++)
#pragma unroll
                for (int j = 0; j < 4; j++)
                    asm volatile(
                        "mma.sync.aligned.m16n8k32.row.col.f32.e4m3.e4m3.f32 "
                        "{%0,%1,%2,%3}, {%4,%5,%6,%7}, {%8,%9}, {%0,%1,%2,%3};"
                        : "+f"(acc[i][j][0]), "+f"(acc[i][j][1]),
                          "+f"(acc[i][j][2]), "+f"(acc[i][j][3])
                        : "r"(a[i][0]), "r"(a[i][1]), "r"(a[i][2]), "r"(a[i][3]),
                          "r"(b[j][0]), "r"(b[j][1]));
        }
        __syncthreads();
        if (it + 2 < iters) load_stage(it & 1, (it + 2) * 128);
    }

    // -------- epilogue --------
    const int rbase = bm + wm + (lane >> 2);
    const int cbase = bn + wn + (lane & 3) * 2;
#pragma unroll
    for (int j = 0; j < 4; j++) {
        const int c = cbase + j * 8;
        const float b0 = bias ? bias[c] : 0.f;
        const float b1 = bias ? bias[c + 1] : 0.f;
        float g0 = 1.f, g1 = 1.f;
        if (EPI == 1) { g0 = gamma[c]; g1 = gamma[c + 1]; }
#pragma unroll
        for (int i = 0; i < 4; i++) {
#pragma unroll
            for (int h = 0; h < 2; h++) {
                const int r = rbase + i * 16 + h * 8;
                const float v0 = acc[i][j][h * 2 + 0] * INV_WSCALE + b0;
                const float v1 = acc[i][j][h * 2 + 1] * INV_WSCALE + b1;
                if (EPI == 0) {
                    bf16* C = (bf16*)Cout;
                    __nv_bfloat162 pv;
                    pv.x = __float2bfloat16(v0);
                    pv.y = __float2bfloat16(v1);
                    *(__nv_bfloat162*)&C[(size_t)r * N + c] = pv;
                } else {
                    float* C = (float*)Cout;
                    float2 rr = *(const float2*)&res[(size_t)r * N + c];
                    float2 o;
                    o.x = rr.x + g0 * v0;
                    o.y = rr.y + g1 * v1;
                    *(float2*)&C[(size_t)r * N + c] = o;
                }
            }
        }
    }
}
#define GEMM_SMEM (STG * 2 * TILEB)

// ---------------- merged weight transpose+convert ----------------
__global__ void wconv_all_kernel(const float* __restrict__ qkv_w, const float* __restrict__ proj_w,
                                 const float* __restrict__ fc1_w, const float* __restrict__ fc2_w,
                                 fp8* __restrict__ wq, fp8* __restrict__ wp,
                                 fp8* __restrict__ w1, fp8* __restrict__ w2) {
    const float* w; fp8* o; int K, N;
    switch (blockIdx.z) {
        case 0: w = qkv_w;  o = wq; K = CDIM; N = 3 * CDIM; break;
        case 1: w = proj_w; o = wp; K = CDIM; N = CDIM;     break;
        case 2: w = fc1_w;  o = w1; K = CDIM; N = HID;      break;
        default:w = fc2_w;  o = w2; K = HID;  N = CDIM;     break;
    }
    const int n0 = blockIdx.x * 32, k0 = blockIdx.y * 32;
    if (n0 >= N || k0 >= K) return;
    __shared__ float tile[32][33];
#pragma unroll
    for (int i = 0; i < 4; i++)
        tile[threadIdx.y + i * 8][threadIdx.x] =
            w[(size_t)(k0 + threadIdx.y + i * 8) * N + n0 + threadIdx.x];
    __syncthreads();
#pragma unroll
    for (int i = 0; i < 4; i++)
        o[(size_t)(n0 + threadIdx.y + i * 8) * K + k0 + threadIdx.x] =
            fp8(tile[threadIdx.x][threadIdx.y + i * 8] * WSCALE);
}

// ---------------- transposes ----------------
__global__ void transpose_in_kernel(const float* __restrict__ x, float* __restrict__ xt) {
    __shared__ float tile[32][33];
    const int b = blockIdx.z, p0 = blockIdx.x * 32, c0 = blockIdx.y * 32;
    const float* xb = x + (size_t)b * CDIM * HWSZ;
#pragma unroll
    for (int i = 0; i < 4; i++)
        tile[threadIdx.y + i * 8][threadIdx.x] =
            xb[(size_t)(c0 + threadIdx.y + i * 8) * HWSZ + p0 + threadIdx.x];
    __syncthreads();
#pragma unroll
    for (int i = 0; i < 4; i++)
        xt[((size_t)b * HWSZ + p0 + threadIdx.y + i * 8) * CDIM + c0 + threadIdx.x] =
            tile[threadIdx.x][threadIdx.y + i * 8];
}
__global__ void transpose_out_kernel(const float* __restrict__ xt, float* __restrict__ out) {
    __shared__ float tile[32][33];
    const int b = blockIdx.z, p0 = blockIdx.x * 32, c0 = blockIdx.y * 32;
#pragma unroll
    for (int i = 0; i < 4; i++)
        tile[threadIdx.y + i * 8][threadIdx.x] =
            xt[((size_t)b * HWSZ + p0 + threadIdx.y + i * 8) * CDIM + c0 + threadIdx.x];
    __syncthreads();
    float* ob = out + (size_t)b * CDIM * HWSZ;
#pragma unroll
    for (int i = 0; i < 4; i++)
        ob[(size_t)(c0 + threadIdx.y + i * 8) * HWSZ + p0 + threadIdx.x] =
            tile[threadIdx.x][threadIdx.y + i * 8];
}

// ---------------- LayerNorm (fp32 in, fp8 out) ----------------
__global__ void ln_kernel(const float* __restrict__ in, fp8* __restrict__ out,
                          const float* __restrict__ g, const float* __restrict__ b) {
    const int row = blockIdx.x * 8 + threadIdx.y;
    const int lane = threadIdx.x;
    const float* xr = in + (size_t)row * CDIM;
    float v[12];
    float s = 0.f;
#pragma unroll
    for (int i = 0; i < 12; i++) { v[i] = xr[lane + i * 32]; s += v[i]; }
#pragma unroll
    for (int o = 16; o > 0; o >>= 1) s += __shfl_xor_sync(0xffffffffu, s, o);
    const float mean = s * (1.f / CDIM);
    float q = 0.f;
#pragma unroll
    for (int i = 0; i < 12; i++) { float d = v[i] - mean; q += d * d; }
#pragma unroll
    for (int o = 16; o > 0; o >>= 1) q += __shfl_xor_sync(0xffffffffu, q, o);
    const float r = rsqrtf(q * (1.f / CDIM) + 1e-5f);
    fp8* orow = out + (size_t)row * CDIM;
#pragma unroll
    for (int i = 0; i < 12; i++) {
        int c = lane + i * 32;
        orow[c] = fp8((v[i] - mean) * r * g[c] + b[c]);
    }
}

// ---------------- attention: packed bf16x2 HFMA2 ----------------
__global__ __launch_bounds__(64) void attn_kernel(const bf16* __restrict__ qkv,
                                                  fp8* __restrict__ o) {
    __shared__ __nv_bfloat162 sk[64][24];
    __shared__ __nv_bfloat162 sv[64][24];
    __shared__ float ss[64][65];
    __shared__ int   srow[64];

    const int wnd  = blockIdx.x;
    const int head = blockIdx.y;
    const int b  = wnd / (GSZ * GSZ);
    const int gy = (wnd / GSZ) % GSZ;
    const int gx = wnd % GSZ;
    const int tid = threadIdx.x;
    {
        int sy = tid / SPR, sx = tid % SPR;
        srow[tid] = b * HWSZ + (sy * GSZ + gy) * HDIM + (sx * GSZ + gx);
    }
    __syncthreads();
    for (int i = tid; i < 64 * 24; i += 64) {
        int t = i / 24, d2 = i % 24;
        size_t base = (size_t)srow[t] * (3 * CDIM) + head * HD + d2 * 2;
        sk[t][d2] = *(const __nv_bfloat162*)&qkv[base + CDIM];
        sv[t][d2] = *(const __nv_bfloat162*)&qkv[base + 2 * CDIM];
    }
    __syncthreads();
    const float scale = 0.14433756729740643f;
    const bf16* qp = qkv + (size_t)srow[tid] * (3 * CDIM) + head * HD;
    __nv_bfloat162 q2[24];
#pragma unroll
    for (int d2 = 0; d2 < 24; d2++) {
        float f0 = __bfloat162float(qp[2 * d2]) * scale;
        float f1 = __bfloat162float(qp[2 * d2 + 1]) * scale;
        q2[d2] = __floats2bfloat162_rn(f0, f1);
    }
    for (int j = 0; j < 64; j++) {
        __nv_bfloat162 a2 = __floats2bfloat162_rn(0.f, 0.f);
#pragma unroll
        for (int d2 = 0; d2 < 24; d2++) a2 = __hfma2(q2[d2], sk[j][d2], a2);
        ss[tid][j] = __low2float(a2) + __high2float(a2);
    }
    float mx = -1e30f;
    for (int j = 0; j < 64; j++) mx = fmaxf(mx, ss[tid][j]);
    float sum = 0.f;
    for (int j = 0; j < 64; j++) {
        float p = expf(ss[tid][j] - mx);
        ss[tid][j] = p; sum += p;
    }
    const float inv = 1.f / sum;
    __nv_bfloat162 oacc[24];
#pragma unroll
    for (int d2 = 0; d2 < 24; d2++) oacc[d2] = __floats2bfloat162_rn(0.f, 0.f);
    for (int j = 0; j < 64; j++) {
        __nv_bfloat162 p2 = __float2bfloat162_rn(ss[tid][j]);
#pragma unroll
        for (int d2 = 0; d2 < 24; d2++) oacc[d2] = __hfma2(p2, sv[j][d2], oacc[d2]);
    }
    fp8* op = o + (size_t)srow[tid] * CDIM + head * HD;
#pragma unroll
    for (int d2 = 0; d2 < 24; d2++) {
        op[2 * d2]     = fp8(__low2float(oacc[d2]) * inv);
        op[2 * d2 + 1] = fp8(__high2float(oacc[d2]) * inv);
    }
}

// ---------------- depthwise 3x3 + GELU, smem row-tiled ----------------
// grid (56 y, 12 ch-chunks, 32 b), 256 threads.
// smem: 3 input rows (y-1,y,y+1) x 56 x x 128 ch (bf16) + packed weights/bias.
__global__ __launch_bounds__(256) void dwconv_gelu_kernel(
    const bf16* __restrict__ m, const float* __restrict__ w,
    const float* __restrict__ bias, fp8* __restrict__ out)
{
    __shared__ __nv_bfloat162 srow[3][56][64];   // 43008 B
    __shared__ __nv_bfloat162 sw[9][64];         // packed weights per channel pair
    __shared__ float2 sb[64];

    const int tid = threadIdx.x;
    const int y   = blockIdx.x;
    const int cc  = blockIdx.y * 128;
    const int b   = blockIdx.z;

    // stage weights + bias
    for (int i = tid; i < 576; i += 256) {       // 9 taps x 64 pairs
        int t = i / 64, cp = i % 64;
        sw[t][cp] = __floats2bfloat162_rn(w[(cc + 2 * cp) * 9 + t],
                                          w[(cc + 2 * cp + 1) * 9 + t]);
    }
    if (tid < 64) sb[tid] = make_float2(bias[cc + 2 * tid], bias[cc + 2 * tid + 1]);

    // stage 3 rows: 56 x * 128 ch * 2B = 896 uint4 per row
    const uint4 zero4 = make_uint4(0, 0, 0, 0);
#pragma unroll
    for (int r = 0; r < 3; r++) {
        int yy = y + r - 1;
        const bool ok = (yy >= 0) && (yy < HDIM);
        const bf16* src = m + ((size_t)b * HWSZ + yy * HDIM) * HID + cc;
        for (int id = tid; id < 896; id += 256) {
            int x = id >> 4, c8 = id & 15;       // 16 uint4 per x
            uint4 v = ok ? *(const uint4*)(src + (size_t)x * HID + c8 * 8) : zero4;
            *(uint4*)&srow[r][x][c8 * 4] = v;
        }
    }
    __syncthreads();

    const float kk = 0.70710678118654752f;
    fp8* orow = out + ((size_t)b * HWSZ + y * HDIM) * HID + cc;

    for (int it = tid; it < 56 * 64; it += 256) {
        int cp = it & 63, x = it >> 6;
        __nv_bfloat162 acc = __floats2bfloat162_rn(0.f, 0.f);
#pragma unroll
        for (int r = 0; r < 3; r++) {
#pragma unroll
            for (int kx = -1; kx <= 1; kx++) {
                int xx = x + kx;
                if (xx >= 0 && xx < HDIM)
                    acc = __hfma2(srow[r][xx][cp], sw[r * 3 + kx + 1][cp], acc);
            }
        }
        float2 bb = sb[cp];
        float a0 = __low2float(acc) + bb.x;
        float a1 = __high2float(acc) + bb.y;
        __nv_fp8x2_e4m3 pv(make_float2(0.5f * a0 * (1.f + erff(a0 * kk)),
                                       0.5f * a1 * (1.f + erff(a1 * kk))));
        *(__nv_fp8x2_e4m3*)&orow[(size_t)x * HID + 2 * cp] = pv;
    }
}

// ---------------- launch ----------------
extern "C" void kernel_launch(void* const* d_in, const int* in_sizes, int n_in,
                              void* d_out, int out_size) {
    const float* x      = (const float*)d_in[0];
    const float* ln1_g  = (const float*)d_in[1];
    const float* ln1_b  = (const float*)d_in[2];
    const float* qkv_w  = (const float*)d_in[3];
    const float* proj_w = (const float*)d_in[4];
    const float* proj_b = (const float*)d_in[5];
    const float* ln2_g  = (const float*)d_in[6];
    const float* ln2_b  = (const float*)d_in[7];
    const float* fc1_w  = (const float*)d_in[8];
    const float* fc1_b  = (const float*)d_in[9];
    const float* dw_w   = (const float*)d_in[10];
    const float* dw_b   = (const float*)d_in[11];
    const float* fc2_w  = (const float*)d_in[12];
    const float* fc2_b  = (const float*)d_in[13];
    const float* gamma1 = (const float*)d_in[14];
    const float* gamma2 = (const float*)d_in[15];
    float* out = (float*)d_out;

    float *xt; bf16 *qkvb, *mb; fp8 *h8, *mg8, *wq, *wp, *w1, *w2;
    cudaGetSymbolAddress((void**)&xt,   g_xt);
    cudaGetSymbolAddress((void**)&h8,   g_h8);
    cudaGetSymbolAddress((void**)&qkvb, g_qkvb);
    cudaGetSymbolAddress((void**)&mb,   g_mb);
    cudaGetSymbolAddress((void**)&mg8,  g_mg8);
    cudaGetSymbolAddress((void**)&wq,   g_wqkv8);
    cudaGetSymbolAddress((void**)&wp,   g_wproj8);
    cudaGetSymbolAddress((void**)&w1,   g_wfc18);
    cudaGetSymbolAddress((void**)&w2,   g_wfc28);

    static bool attr_done = false;
    if (!attr_done) {
        cudaFuncSetAttribute(gemm_fp8_kernel<0>,
                             cudaFuncAttributeMaxDynamicSharedMemorySize, GEMM_SMEM);
        cudaFuncSetAttribute(gemm_fp8_kernel<1>,
                             cudaFuncAttributeMaxDynamicSharedMemorySize, GEMM_SMEM);
        attr_done = true;
    }

    dim3 tb32x8(32, 8);

    wconv_all_kernel<<<dim3(48, 48, 4), tb32x8>>>(qkv_w, proj_w, fc1_w, fc2_w,
                                                  wq, wp, w1, w2);
    transpose_in_kernel<<<dim3(HWSZ / 32, CDIM / 32, BATCH), tb32x8>>>(x, xt);
    ln_kernel<<<NTOK / 8, tb32x8>>>(xt, h8, ln1_g, ln1_b);

    gemm_fp8_kernel<0><<<dim3(1152 / 128, NTOK / 128), 256, GEMM_SMEM>>>(
        h8, wq, nullptr, nullptr, nullptr, qkvb, NTOK, 1152, CDIM);
    attn_kernel<<<dim3(BATCH * GSZ * GSZ, HEADS), 64>>>(qkvb, h8);
    gemm_fp8_kernel<1><<<dim3(CDIM / 128, NTOK / 128), 256, GEMM_SMEM>>>(
        h8, wp, proj_b, xt, gamma1, xt, NTOK, CDIM, CDIM);
    ln_kernel<<<NTOK / 8, tb32x8>>>(xt, h8, ln2_g, ln2_b);
    gemm_fp8_kernel<0><<<dim3(HID / 128, NTOK / 128), 256, GEMM_SMEM>>>(
        h8, w1, fc1_b, nullptr, nullptr, mb, NTOK, HID, CDIM);
    dwconv_gelu_kernel<<<dim3(HDIM, HID / 128, BATCH), 256>>>(mb, dw_w, dw_b, mg8);
    gemm_fp8_kernel<1><<<dim3(CDIM / 128, NTOK / 128), 256, GEMM_SMEM>>>(
        mg8, w2, fc2_b, xt, gamma2, xt, NTOK, CDIM, HID);

    transpose_out_kernel<<<dim3(HWSZ / 32, CDIM / 32, BATCH), tb32x8>>>(xt, out);
}

// round 10
// speedup vs baseline: 4.2006x; 1.1149x over previous
#include <cuda_runtime.h>
#include <cuda_bf16.h>
#include <cuda_fp8.h>
#include <cstdint>
#include <math.h>

#define BATCH 32
#define CDIM  384
#define HDIM  56
#define HWSZ  3136
#define NTOK  100352
#define HID   1536
#define HEADS 8
#define HD    48
#define GSZ   7
#define SPR   8

typedef __nv_bfloat16 bf16;
typedef __nv_fp8_e4m3 fp8;

#define WSCALE     64.0f
#define INV_WSCALE 0.015625f

// ---------------- scratch ----------------
__device__ float g_xt  [(size_t)NTOK * CDIM];
__device__ fp8   g_h8  [(size_t)NTOK * CDIM];
__device__ bf16  g_qkvb[(size_t)NTOK * 3 * CDIM];
__device__ bf16  g_mb  [(size_t)NTOK * HID];
__device__ fp8   g_mg8 [(size_t)NTOK * HID];
__device__ fp8   g_wqkv8 [3 * CDIM * CDIM];
__device__ fp8   g_wproj8[CDIM * CDIM];
__device__ fp8   g_wfc18 [HID * CDIM];
__device__ fp8   g_wfc28 [CDIM * HID];

__device__ __forceinline__ unsigned int saddr(const void* p) {
    return (unsigned int)__cvta_generic_to_shared(p);
}
__device__ __forceinline__ void cp16(unsigned int dst, const void* src) {
    asm volatile("cp.async.cg.shared.global [%0], [%1], 16;" :: "r"(dst), "l"(src));
}

// ================== FP8 e4m3 tensor-core GEMM ==================
// Block 128x128, 8 warps (warp tile 64x32), BK=128 bytes, 2-stage ring, 2 CTAs/SM.
#define PADB 144
#define STG 2
#define TILEB (128 * PADB)

template<int EPI>
__global__ __launch_bounds__(256, 2) void gemm_fp8_kernel(
    const fp8* __restrict__ A, const fp8* __restrict__ Bw,
    const float* __restrict__ bias, const float* __restrict__ res,
    const float* __restrict__ gamma, void* __restrict__ Cout,
    int M, int N, int K)
{
    extern __shared__ char sm8[];
    char* As = sm8;
    char* Bs = sm8 + STG * TILEB;

    const int tid  = threadIdx.x;
    const int lane = tid & 31;
    const int warp = tid >> 5;
    const int wm   = (warp >> 2) * 64;
    const int wn   = (warp & 3) * 32;
    const int bm   = blockIdx.y * 128;
    const int bn   = blockIdx.x * 128;

    float acc[4][4][4];
#pragma unroll
    for (int i = 0; i < 4; i++)
#pragma unroll
        for (int j = 0; j < 4; j++)
#pragma unroll
            for (int r = 0; r < 4; r++) acc[i][j][r] = 0.f;

    const int a_row  = lane & 15;
    const int a_kb   = (lane >> 4) * 16;
    const int b_nrow = ((lane >> 4) * 8) + (lane & 7);
    const int b_kb   = ((lane >> 3) & 1) * 16;

    const int iters = K / 128;

    auto load_stage = [&](int s, int k0) {
        char* as = As + s * TILEB;
        char* bs = Bs + s * TILEB;
#pragma unroll
        for (int u = 0; u < 4; u++) {
            int id = u * 256 + tid;
            int row = id >> 3, c = id & 7;
            cp16(saddr(as + row * PADB + c * 16),
                 (const char*)A + (size_t)(bm + row) * K + k0 + c * 16);
        }
#pragma unroll
        for (int u = 0; u < 4; u++) {
            int id = u * 256 + tid;
            int row = id >> 3, c = id & 7;
            cp16(saddr(bs + row * PADB + c * 16),
                 (const char*)Bw + (size_t)(bn + row) * K + k0 + c * 16);
        }
        asm volatile("cp.async.commit_group;");
    };

    load_stage(0, 0);
    if (iters > 1) load_stage(1, 128);

    for (int it = 0; it < iters; it++) {
        if (it + 1 < iters)
            asm volatile("cp.async.wait_group 1;" ::: "memory");
        else
            asm volatile("cp.async.wait_group 0;" ::: "memory");
        __syncthreads();

        const char* as = As + (it & 1) * TILEB;
        const char* bs = Bs + (it & 1) * TILEB;

#pragma unroll
        for (int ks = 0; ks < 4; ks++) {
            unsigned int a[4][4];
#pragma unroll
            for (int i = 0; i < 4; i++) {
                unsigned int ad = saddr(as + (wm + i * 16 + a_row) * PADB + ks * 32 + a_kb);
                asm volatile("ldmatrix.sync.aligned.m8n8.x4.shared.b16 {%0,%1,%2,%3}, [%4];"
                             : "=r"(a[i][0]), "=r"(a[i][1]), "=r"(a[i][2]), "=r"(a[i][3])
                             : "r"(ad));
            }
            unsigned int b[4][2];
#pragma unroll
            for (int j2 = 0; j2 < 2; j2++) {
                unsigned int bd = saddr(bs + (wn + j2 * 16 + b_nrow) * PADB + ks * 32 + b_kb);
                unsigned int r0, r1, r2, r3;
                asm volatile("ldmatrix.sync.aligned.m8n8.x4.shared.b16 {%0,%1,%2,%3}, [%4];"
                             : "=r"(r0), "=r"(r1), "=r"(r2), "=r"(r3) : "r"(bd));
                b[j2 * 2 + 0][0] = r0; b[j2 * 2 + 0][1] = r1;
                b[j2 * 2 + 1][0] = r2; b[j2 * 2 + 1][1] = r3;
            }
#pragma unroll
            for (int i = 0; i < 4; i++)
#pragma unroll
                for (int j = 0; j < 4; j++)
                    asm volatile(
                        "mma.sync.aligned.m16n8k32.row.col.f32.e4m3.e4m3.f32 "
                        "{%0,%1,%2,%3}, {%4,%5,%6,%7}, {%8,%9}, {%0,%1,%2,%3};"
                        : "+f"(acc[i][j][0]), "+f"(acc[i][j][1]),
                          "+f"(acc[i][j][2]), "+f"(acc[i][j][3])
                        : "r"(a[i][0]), "r"(a[i][1]), "r"(a[i][2]), "r"(a[i][3]),
                          "r"(b[j][0]), "r"(b[j][1]));
        }
        __syncthreads();
        if (it + 2 < iters) load_stage(it & 1, (it + 2) * 128);
    }

    // -------- epilogue --------
    const int rbase = bm + wm + (lane >> 2);
    const int cbase = bn + wn + (lane & 3) * 2;
#pragma unroll
    for (int j = 0; j < 4; j++) {
        const int c = cbase + j * 8;
        const float b0 = bias ? bias[c] : 0.f;
        const float b1 = bias ? bias[c + 1] : 0.f;
        float g0 = 1.f, g1 = 1.f;
        if (EPI == 1) { g0 = gamma[c]; g1 = gamma[c + 1]; }
#pragma unroll
        for (int i = 0; i < 4; i++) {
#pragma unroll
            for (int h = 0; h < 2; h++) {
                const int r = rbase + i * 16 + h * 8;
                const float v0 = acc[i][j][h * 2 + 0] * INV_WSCALE + b0;
                const float v1 = acc[i][j][h * 2 + 1] * INV_WSCALE + b1;
                if (EPI == 0) {
                    bf16* C = (bf16*)Cout;
                    __nv_bfloat162 pv;
                    pv.x = __float2bfloat16(v0);
                    pv.y = __float2bfloat16(v1);
                    *(__nv_bfloat162*)&C[(size_t)r * N + c] = pv;
                } else {
                    float* C = (float*)Cout;
                    float2 rr = *(const float2*)&res[(size_t)r * N + c];
                    float2 o;
                    o.x = rr.x + g0 * v0;
                    o.y = rr.y + g1 * v1;
                    *(float2*)&C[(size_t)r * N + c] = o;
                }
            }
        }
    }
}
#define GEMM_SMEM (STG * 2 * TILEB)

// ---------------- merged weight transpose+convert ----------------
__global__ void wconv_all_kernel(const float* __restrict__ qkv_w, const float* __restrict__ proj_w,
                                 const float* __restrict__ fc1_w, const float* __restrict__ fc2_w,
                                 fp8* __restrict__ wq, fp8* __restrict__ wp,
                                 fp8* __restrict__ w1, fp8* __restrict__ w2) {
    const float* w; fp8* o; int K, N;
    switch (blockIdx.z) {
        case 0: w = qkv_w;  o = wq; K = CDIM; N = 3 * CDIM; break;
        case 1: w = proj_w; o = wp; K = CDIM; N = CDIM;     break;
        case 2: w = fc1_w;  o = w1; K = CDIM; N = HID;      break;
        default:w = fc2_w;  o = w2; K = HID;  N = CDIM;     break;
    }
    const int n0 = blockIdx.x * 32, k0 = blockIdx.y * 32;
    if (n0 >= N || k0 >= K) return;
    __shared__ float tile[32][33];
#pragma unroll
    for (int i = 0; i < 4; i++)
        tile[threadIdx.y + i * 8][threadIdx.x] =
            w[(size_t)(k0 + threadIdx.y + i * 8) * N + n0 + threadIdx.x];
    __syncthreads();
#pragma unroll
    for (int i = 0; i < 4; i++)
        o[(size_t)(n0 + threadIdx.y + i * 8) * K + k0 + threadIdx.x] =
            fp8(tile[threadIdx.x][threadIdx.y + i * 8] * WSCALE);
}

// ---------------- transposes ----------------
__global__ void transpose_in_kernel(const float* __restrict__ x, float* __restrict__ xt) {
    __shared__ float tile[32][33];
    const int b = blockIdx.z, p0 = blockIdx.x * 32, c0 = blockIdx.y * 32;
    const float* xb = x + (size_t)b * CDIM * HWSZ;
#pragma unroll
    for (int i = 0; i < 4; i++)
        tile[threadIdx.y + i * 8][threadIdx.x] =
            xb[(size_t)(c0 + threadIdx.y + i * 8) * HWSZ + p0 + threadIdx.x];
    __syncthreads();
#pragma unroll
    for (int i = 0; i < 4; i++)
        xt[((size_t)b * HWSZ + p0 + threadIdx.y + i * 8) * CDIM + c0 + threadIdx.x] =
            tile[threadIdx.x][threadIdx.y + i * 8];
}
__global__ void transpose_out_kernel(const float* __restrict__ xt, float* __restrict__ out) {
    __shared__ float tile[32][33];
    const int b = blockIdx.z, p0 = blockIdx.x * 32, c0 = blockIdx.y * 32;
#pragma unroll
    for (int i = 0; i < 4; i++)
        tile[threadIdx.y + i * 8][threadIdx.x] =
            xt[((size_t)b * HWSZ + p0 + threadIdx.y + i * 8) * CDIM + c0 + threadIdx.x];
    __syncthreads();
    float* ob = out + (size_t)b * CDIM * HWSZ;
#pragma unroll
    for (int i = 0; i < 4; i++)
        ob[(size_t)(c0 + threadIdx.y + i * 8) * HWSZ + p0 + threadIdx.x] =
            tile[threadIdx.x][threadIdx.y + i * 8];
}

// ---------------- LayerNorm (fp32 in, fp8 out) ----------------
__global__ void ln_kernel(const float* __restrict__ in, fp8* __restrict__ out,
                          const float* __restrict__ g, const float* __restrict__ b) {
    const int row = blockIdx.x * 8 + threadIdx.y;
    const int lane = threadIdx.x;
    const float* xr = in + (size_t)row * CDIM;
    float v[12];
    float s = 0.f;
#pragma unroll
    for (int i = 0; i < 12; i++) { v[i] = xr[lane + i * 32]; s += v[i]; }
#pragma unroll
    for (int o = 16; o > 0; o >>= 1) s += __shfl_xor_sync(0xffffffffu, s, o);
    const float mean = s * (1.f / CDIM);
    float q = 0.f;
#pragma unroll
    for (int i = 0; i < 12; i++) { float d = v[i] - mean; q += d * d; }
#pragma unroll
    for (int o = 16; o > 0; o >>= 1) q += __shfl_xor_sync(0xffffffffu, q, o);
    const float r = rsqrtf(q * (1.f / CDIM) + 1e-5f);
    fp8* orow = out + (size_t)row * CDIM;
#pragma unroll
    for (int i = 0; i < 12; i++) {
        int c = lane + i * 32;
        orow[c] = fp8((v[i] - mean) * r * g[c] + b[c]);
    }
}

// ---------------- attention: packed bf16x2 HFMA2 ----------------
__global__ __launch_bounds__(64) void attn_kernel(const bf16* __restrict__ qkv,
                                                  fp8* __restrict__ o) {
    __shared__ __nv_bfloat162 sk[64][24];
    __shared__ __nv_bfloat162 sv[64][24];
    __shared__ float ss[64][65];
    __shared__ int   srow[64];

    const int wnd  = blockIdx.x;
    const int head = blockIdx.y;
    const int b  = wnd / (GSZ * GSZ);
    const int gy = (wnd / GSZ) % GSZ;
    const int gx = wnd % GSZ;
    const int tid = threadIdx.x;
    {
        int sy = tid / SPR, sx = tid % SPR;
        srow[tid] = b * HWSZ + (sy * GSZ + gy) * HDIM + (sx * GSZ + gx);
    }
    __syncthreads();
    for (int i = tid; i < 64 * 24; i += 64) {
        int t = i / 24, d2 = i % 24;
        size_t base = (size_t)srow[t] * (3 * CDIM) + head * HD + d2 * 2;
        sk[t][d2] = *(const __nv_bfloat162*)&qkv[base + CDIM];
        sv[t][d2] = *(const __nv_bfloat162*)&qkv[base + 2 * CDIM];
    }
    __syncthreads();
    const float scale = 0.14433756729740643f;
    const bf16* qp = qkv + (size_t)srow[tid] * (3 * CDIM) + head * HD;
    __nv_bfloat162 q2[24];
#pragma unroll
    for (int d2 = 0; d2 < 24; d2++) {
        float f0 = __bfloat162float(qp[2 * d2]) * scale;
        float f1 = __bfloat162float(qp[2 * d2 + 1]) * scale;
        q2[d2] = __floats2bfloat162_rn(f0, f1);
    }
    for (int j = 0; j < 64; j++) {
        __nv_bfloat162 a2 = __floats2bfloat162_rn(0.f, 0.f);
#pragma unroll
        for (int d2 = 0; d2 < 24; d2++) a2 = __hfma2(q2[d2], sk[j][d2], a2);
        ss[tid][j] = __low2float(a2) + __high2float(a2);
    }
    float mx = -1e30f;
    for (int j = 0; j < 64; j++) mx = fmaxf(mx, ss[tid][j]);
    float sum = 0.f;
    for (int j = 0; j < 64; j++) {
        float p = expf(ss[tid][j] - mx);
        ss[tid][j] = p; sum += p;
    }
    const float inv = 1.f / sum;
    __nv_bfloat162 oacc[24];
#pragma unroll
    for (int d2 = 0; d2 < 24; d2++) oacc[d2] = __floats2bfloat162_rn(0.f, 0.f);
    for (int j = 0; j < 64; j++) {
        __nv_bfloat162 p2 = __float2bfloat162_rn(ss[tid][j]);
#pragma unroll
        for (int d2 = 0; d2 < 24; d2++) oacc[d2] = __hfma2(p2, sv[j][d2], oacc[d2]);
    }
    fp8* op = o + (size_t)srow[tid] * CDIM + head * HD;
#pragma unroll
    for (int d2 = 0; d2 < 24; d2++) {
        op[2 * d2]     = fp8(__low2float(oacc[d2]) * inv);
        op[2 * d2 + 1] = fp8(__high2float(oacc[d2]) * inv);
    }
}

// ---------------- depthwise 3x3 + GELU, smem row-tiled ----------------
__global__ __launch_bounds__(256) void dwconv_gelu_kernel(
    const bf16* __restrict__ m, const float* __restrict__ w,
    const float* __restrict__ bias, fp8* __restrict__ out)
{
    __shared__ __nv_bfloat162 srow[3][56][64];
    __shared__ __nv_bfloat162 sw[9][64];
    __shared__ float2 sb[64];

    const int tid = threadIdx.x;
    const int y   = blockIdx.x;
    const int cc  = blockIdx.y * 128;
    const int b   = blockIdx.z;

    for (int i = tid; i < 576; i += 256) {
        int t = i / 64, cp = i % 64;
        sw[t][cp] = __floats2bfloat162_rn(w[(cc + 2 * cp) * 9 + t],
                                          w[(cc + 2 * cp + 1) * 9 + t]);
    }
    if (tid < 64) sb[tid] = make_float2(bias[cc + 2 * tid], bias[cc + 2 * tid + 1]);

    const uint4 zero4 = make_uint4(0, 0, 0, 0);
#pragma unroll
    for (int r = 0; r < 3; r++) {
        int yy = y + r - 1;
        const bool ok = (yy >= 0) && (yy < HDIM);
        const bf16* src = m + ((size_t)b * HWSZ + yy * HDIM) * HID + cc;
        for (int id = tid; id < 896; id += 256) {
            int x = id >> 4, c8 = id & 15;
            uint4 v = ok ? *(const uint4*)(src + (size_t)x * HID + c8 * 8) : zero4;
            *(uint4*)&srow[r][x][c8 * 4] = v;
        }
    }
    __syncthreads();

    const float kk = 0.70710678118654752f;
    fp8* orow = out + ((size_t)b * HWSZ + y * HDIM) * HID + cc;

    for (int it = tid; it < 56 * 64; it += 256) {
        int cp = it & 63, x = it >> 6;
        __nv_bfloat162 acc = __floats2bfloat162_rn(0.f, 0.f);
#pragma unroll
        for (int r = 0; r < 3; r++) {
#pragma unroll
            for (int kx = -1; kx <= 1; kx++) {
                int xx = x + kx;
                if (xx >= 0 && xx < HDIM)
                    acc = __hfma2(srow[r][xx][cp], sw[r * 3 + kx + 1][cp], acc);
            }
        }
        float2 bb = sb[cp];
        float a0 = __low2float(acc) + bb.x;
        float a1 = __high2float(acc) + bb.y;
        __nv_fp8x2_e4m3 pv(make_float2(0.5f * a0 * (1.f + erff(a0 * kk)),
                                       0.5f * a1 * (1.f + erff(a1 * kk))));
        *(__nv_fp8x2_e4m3*)&orow[(size_t)x * HID + 2 * cp] = pv;
    }
}

// ---------------- launch ----------------
extern "C" void kernel_launch(void* const* d_in, const int* in_sizes, int n_in,
                              void* d_out, int out_size) {
    const float* x      = (const float*)d_in[0];
    const float* ln1_g  = (const float*)d_in[1];
    const float* ln1_b  = (const float*)d_in[2];
    const float* qkv_w  = (const float*)d_in[3];
    const float* proj_w = (const float*)d_in[4];
    const float* proj_b = (const float*)d_in[5];
    const float* ln2_g  = (const float*)d_in[6];
    const float* ln2_b  = (const float*)d_in[7];
    const float* fc1_w  = (const float*)d_in[8];
    const float* fc1_b  = (const float*)d_in[9];
    const float* dw_w   = (const float*)d_in[10];
    const float* dw_b   = (const float*)d_in[11];
    const float* fc2_w  = (const float*)d_in[12];
    const float* fc2_b  = (const float*)d_in[13];
    const float* gamma1 = (const float*)d_in[14];
    const float* gamma2 = (const float*)d_in[15];
    float* out = (float*)d_out;

    float *xt; bf16 *qkvb, *mb; fp8 *h8, *mg8, *wq, *wp, *w1, *w2;
    cudaGetSymbolAddress((void**)&xt,   g_xt);
    cudaGetSymbolAddress((void**)&h8,   g_h8);
    cudaGetSymbolAddress((void**)&qkvb, g_qkvb);
    cudaGetSymbolAddress((void**)&mb,   g_mb);
    cudaGetSymbolAddress((void**)&mg8,  g_mg8);
    cudaGetSymbolAddress((void**)&wq,   g_wqkv8);
    cudaGetSymbolAddress((void**)&wp,   g_wproj8);
    cudaGetSymbolAddress((void**)&w1,   g_wfc18);
    cudaGetSymbolAddress((void**)&w2,   g_wfc28);

    static bool attr_done = false;
    if (!attr_done) {
        cudaFuncSetAttribute(gemm_fp8_kernel<0>,
                             cudaFuncAttributeMaxDynamicSharedMemorySize, GEMM_SMEM);
        cudaFuncSetAttribute(gemm_fp8_kernel<1>,
                             cudaFuncAttributeMaxDynamicSharedMemorySize, GEMM_SMEM);
        attr_done = true;
    }

    dim3 tb32x8(32, 8);

    wconv_all_kernel<<<dim3(48, 48, 4), tb32x8>>>(qkv_w, proj_w, fc1_w, fc2_w,
                                                  wq, wp, w1, w2);
    transpose_in_kernel<<<dim3(HWSZ / 32, CDIM / 32, BATCH), tb32x8>>>(x, xt);
    ln_kernel<<<NTOK / 8, tb32x8>>>(xt, h8, ln1_g, ln1_b);

    gemm_fp8_kernel<0><<<dim3(1152 / 128, NTOK / 128), 256, GEMM_SMEM>>>(
        h8, wq, nullptr, nullptr, nullptr, qkvb, NTOK, 1152, CDIM);
    attn_kernel<<<dim3(BATCH * GSZ * GSZ, HEADS), 64>>>(qkvb, h8);
    gemm_fp8_kernel<1><<<dim3(CDIM / 128, NTOK / 128), 256, GEMM_SMEM>>>(
        h8, wp, proj_b, xt, gamma1, xt, NTOK, CDIM, CDIM);
    ln_kernel<<<NTOK / 8, tb32x8>>>(xt, h8, ln2_g, ln2_b);
    gemm_fp8_kernel<0><<<dim3(HID / 128, NTOK / 128), 256, GEMM_SMEM>>>(
        h8, w1, fc1_b, nullptr, nullptr, mb, NTOK, HID, CDIM);
    dwconv_gelu_kernel<<<dim3(HDIM, HID / 128, BATCH), 256>>>(mb, dw_w, dw_b, mg8);
    gemm_fp8_kernel<1><<<dim3(CDIM / 128, NTOK / 128), 256, GEMM_SMEM>>>(
        mg8, w2, fc2_b, xt, gamma2, xt, NTOK, CDIM, HID);

    transpose_out_kernel<<<dim3(HWSZ / 32, CDIM / 32, BATCH), tb32x8>>>(xt, out);
}